// round 1
// baseline (speedup 1.0000x reference)
#include <cuda_runtime.h>
#include <math.h>

#define BB 64
#define TT 512
#define VV 32000
#define DD 512
#define HH 1024
#define G4 4096  // 4*H

// Scratch (allocation-free rule: __device__ globals only)
__device__ float g_xw[(size_t)BB * TT * G4];   // 512 MB: xw = E[ids]@W + b, laid out [b][t][4H]
__device__ float g_h[2][BB * HH];              // ping-pong hidden state
__device__ float g_c[BB * HH];                 // cell state

__device__ __forceinline__ float sigf(float x) {
    return 1.0f / (1.0f + __expf(-x));
}

// ---------------------------------------------------------------------------
// init: zero h (buffer 0) and c
// ---------------------------------------------------------------------------
__global__ void init_state() {
    int i = blockIdx.x * blockDim.x + threadIdx.x;
    if (i < BB * HH) {
        g_h[0][i] = 0.0f;
        g_c[i] = 0.0f;
    }
}

// ---------------------------------------------------------------------------
// GEMM1: xw[m][n] = sum_k E[ids[m]][k] * W[k][n] + bias[n]
// M=32768, N=4096, K=512.  128x128 tile, BK=8, 256 threads, 8x8 microtile.
// ---------------------------------------------------------------------------
__global__ __launch_bounds__(256) void embed_gemm(
    const int* __restrict__ ids,
    const float* __restrict__ E,
    const float* __restrict__ W,
    const float* __restrict__ bias)
{
    __shared__ float As[8][132];   // A tile transposed: As[k][m], padded
    __shared__ float Bs[8][128];   // Bs[k][n]
    __shared__ int ids_s[128];

    const int m0 = blockIdx.y * 128;
    const int n0 = blockIdx.x * 128;
    const int tid = threadIdx.x;

    if (tid < 128) ids_s[tid] = ids[m0 + tid];
    __syncthreads();

    const int tx = tid & 15;        // 0..15  -> 8 cols (two groups of 4)
    const int ty = tid >> 4;        // 0..15  -> 8 rows (two groups of 4)

    const int ar = tid >> 1;        // 0..127 : A tile row
    const int ak = (tid & 1) * 4;   // 0 or 4 : A k-quad
    const int bk = tid >> 5;        // 0..7   : B tile k
    const int bc = (tid & 31) * 4;  // 0..124 : B col quad

    float acc[8][8];
#pragma unroll
    for (int i = 0; i < 8; i++)
#pragma unroll
        for (int j = 0; j < 8; j++) acc[i][j] = 0.0f;

    for (int k0 = 0; k0 < DD; k0 += 8) {
        float4 av = *(const float4*)&E[(size_t)ids_s[ar] * DD + k0 + ak];
        float4 bv = *(const float4*)&W[(size_t)(k0 + bk) * G4 + n0 + bc];

        __syncthreads();  // previous compute done before overwrite
        As[ak + 0][ar] = av.x;
        As[ak + 1][ar] = av.y;
        As[ak + 2][ar] = av.z;
        As[ak + 3][ar] = av.w;
        *(float4*)&Bs[bk][bc] = bv;
        __syncthreads();

#pragma unroll
        for (int k = 0; k < 8; k++) {
            float4 a0 = *(float4*)&As[k][ty * 4];
            float4 a1 = *(float4*)&As[k][64 + ty * 4];
            float4 b0 = *(float4*)&Bs[k][tx * 4];
            float4 b1 = *(float4*)&Bs[k][64 + tx * 4];
            float a[8] = {a0.x, a0.y, a0.z, a0.w, a1.x, a1.y, a1.z, a1.w};
            float b[8] = {b0.x, b0.y, b0.z, b0.w, b1.x, b1.y, b1.z, b1.w};
#pragma unroll
            for (int i = 0; i < 8; i++)
#pragma unroll
                for (int j = 0; j < 8; j++)
                    acc[i][j] = fmaf(a[i], b[j], acc[i][j]);
        }
    }

    // epilogue: add bias, store to g_xw
    float bval[8];
#pragma unroll
    for (int jj = 0; jj < 2; jj++) {
        float4 bv = *(const float4*)&bias[n0 + jj * 64 + tx * 4];
        bval[jj * 4 + 0] = bv.x; bval[jj * 4 + 1] = bv.y;
        bval[jj * 4 + 2] = bv.z; bval[jj * 4 + 3] = bv.w;
    }
#pragma unroll
    for (int ii = 0; ii < 2; ii++) {
#pragma unroll
        for (int i = 0; i < 4; i++) {
            int row = m0 + ii * 64 + ty * 4 + i;
#pragma unroll
            for (int jj = 0; jj < 2; jj++) {
                float4 v;
                v.x = acc[ii * 4 + i][jj * 4 + 0] + bval[jj * 4 + 0];
                v.y = acc[ii * 4 + i][jj * 4 + 1] + bval[jj * 4 + 1];
                v.z = acc[ii * 4 + i][jj * 4 + 2] + bval[jj * 4 + 2];
                v.w = acc[ii * 4 + i][jj * 4 + 3] + bval[jj * 4 + 3];
                *(float4*)&g_xw[(size_t)row * G4 + n0 + jj * 64 + tx * 4] = v;
            }
        }
    }
}

// ---------------------------------------------------------------------------
// One recurrence step. grid = 128 blocks (each owns 8 h-columns), 128 threads.
// Block computes z[b][c] for all b (64) and 32 z-columns = {i,f,g,o} x 8 j's,
// then applies gates and writes h/c/outs.
// ---------------------------------------------------------------------------
__global__ __launch_bounds__(128) void lstm_step(
    const int* __restrict__ ids,
    const float* __restrict__ U,
    float* __restrict__ outs,
    int t)
{
    const float* __restrict__ h_in = g_h[t & 1];
    float* __restrict__ h_out = g_h[(t + 1) & 1];

    __shared__ float As[16][68];     // h tile transposed: As[k][b]
    __shared__ float Bs[16][32];     // U tile: Bs[k][c], c = gate*8 + jj
    __shared__ float zs[64][33];     // z tile for gate fusion

    const int tid = threadIdx.x;
    const int j0 = blockIdx.x * 8;
    const int tx = tid & 7;          // 4 z-cols: tx*4..tx*4+3
    const int ty = tid >> 3;         // 4 batch rows: ty*4..ty*4+3

    // B-load mapping (1 float4 per thread per stage)
    const int kb = tid >> 3;                 // 0..15
    const int c4 = (tid & 7) * 4;            // 0..28 step 4
    const int gate = c4 >> 3;                // 0..3
    const int jjq = c4 & 7;                  // 0 or 4

    float acc[4][4];
#pragma unroll
    for (int i = 0; i < 4; i++)
#pragma unroll
        for (int j = 0; j < 4; j++) acc[i][j] = 0.0f;

    for (int k0 = 0; k0 < HH; k0 += 16) {
        float4 av[2];
#pragma unroll
        for (int p = 0; p < 2; p++) {
            int q = tid + p * 128;
            int b_ = q >> 2;
            int k4 = (q & 3) * 4;
            av[p] = *(const float4*)&h_in[b_ * HH + k0 + k4];
        }
        float4 bv = *(const float4*)&U[(size_t)(k0 + kb) * G4 + gate * HH + j0 + jjq];

        __syncthreads();
#pragma unroll
        for (int p = 0; p < 2; p++) {
            int q = tid + p * 128;
            int b_ = q >> 2;
            int k4 = (q & 3) * 4;
            As[k4 + 0][b_] = av[p].x;
            As[k4 + 1][b_] = av[p].y;
            As[k4 + 2][b_] = av[p].z;
            As[k4 + 3][b_] = av[p].w;
        }
        *(float4*)&Bs[kb][c4] = bv;
        __syncthreads();

#pragma unroll
        for (int k = 0; k < 16; k++) {
            float4 a = *(float4*)&As[k][ty * 4];
            float4 bb = *(float4*)&Bs[k][tx * 4];
            float ar[4] = {a.x, a.y, a.z, a.w};
            float br[4] = {bb.x, bb.y, bb.z, bb.w};
#pragma unroll
            for (int i = 0; i < 4; i++)
#pragma unroll
                for (int j = 0; j < 4; j++)
                    acc[i][j] = fmaf(ar[i], br[j], acc[i][j]);
        }
    }

    __syncthreads();
#pragma unroll
    for (int i = 0; i < 4; i++)
#pragma unroll
        for (int j = 0; j < 4; j++)
            zs[ty * 4 + i][tx * 4 + j] = acc[i][j];
    __syncthreads();

    // Gate fusion: 512 (b, jj) items, 4 per thread
#pragma unroll
    for (int p = 0; p < 4; p++) {
        int idx = tid + p * 128;
        int jj = idx & 7;
        int b_ = idx >> 3;
        size_t xbase = ((size_t)(b_ * TT + t)) * G4 + j0 + jj;
        float zi = zs[b_][jj]          + g_xw[xbase];
        float zf = zs[b_][8 + jj]      + g_xw[xbase + HH];
        float zg = zs[b_][16 + jj]     + g_xw[xbase + 2 * HH];
        float zo = zs[b_][24 + jj]     + g_xw[xbase + 3 * HH];

        float ig = sigf(zi);
        float fg = sigf(zf);
        float gg = sigf(zg);   // reference uses sigmoid here (not tanh)
        float og = sigf(zo);

        int hidx = b_ * HH + j0 + jj;
        float cold = g_c[hidx];
        float hold = h_in[hidx];

        float cn = fmaf(fg, cold, ig * gg);
        float hn = og * sigf(cn);  // reference: o * sigmoid(c_new)

        bool m = ids[b_ * TT + t] != 0;
        float hv = m ? hn : hold;
        float cv = m ? cn : cold;

        h_out[hidx] = hv;
        g_c[hidx] = cv;
        outs[((size_t)(b_ * TT + t)) * HH + j0 + jj] = hv;
    }
}

// ---------------------------------------------------------------------------
// finalize: append hF, cF after outs
// ---------------------------------------------------------------------------
__global__ void finalize(float* __restrict__ out) {
    int i = blockIdx.x * blockDim.x + threadIdx.x;
    if (i < BB * HH) {
        out[(size_t)BB * TT * HH + i] = g_h[0][i];           // h after t=511 is in buffer 0
        out[(size_t)BB * TT * HH + BB * HH + i] = g_c[i];
    }
}

extern "C" void kernel_launch(void* const* d_in, const int* in_sizes, int n_in,
                              void* d_out, int out_size) {
    const int*   ids  = (const int*)d_in[0];
    const float* E    = (const float*)d_in[1];
    const float* W    = (const float*)d_in[2];
    const float* U    = (const float*)d_in[3];
    const float* bias = (const float*)d_in[4];
    float* out = (float*)d_out;

    // 1. zero h0, c0
    init_state<<<(BB * HH + 255) / 256, 256>>>();

    // 2. xw = E[ids] @ W + b
    dim3 g1(G4 / 128, (BB * TT) / 128);  // (32, 256)
    embed_gemm<<<g1, 256>>>(ids, E, W, bias);

    // 3. 512 sequential recurrence steps
    for (int t = 0; t < TT; t++) {
        lstm_step<<<HH / 8, 128>>>(ids, U, out, t);
    }

    // 4. append final h, c
    finalize<<<(BB * HH + 255) / 256, 256>>>(out);
}

// round 2
// speedup vs baseline: 1.8807x; 1.8807x over previous
#include <cuda_runtime.h>
#include <math.h>
#include <stdint.h>

#define BB 64
#define TT 512
#define VV 32000
#define DD 512
#define HH 1024
#define G4 4096  // 4*H

// Scratch (allocation-free rule: __device__ globals only)
__device__ float  g_xw[(size_t)BB * TT * G4];   // 512 MB: xw = E[ids]@W + b
__device__ float  g_h[2][BB * HH];              // ping-pong hidden state
__device__ float  g_c[BB * HH];                 // cell state
__device__ float2 g_Upack[128 * 4 * 128 * 32];  // 16 MB: U in mma-fragment layout (tf32)

__device__ __forceinline__ float sigf(float x) {
    return 1.0f / (1.0f + __expf(-x));
}

__device__ __forceinline__ void mma_tf32(float d[4],
                                         uint32_t a0, uint32_t a1, uint32_t a2, uint32_t a3,
                                         uint32_t b0, uint32_t b1) {
    asm volatile(
        "mma.sync.aligned.m16n8k8.row.col.f32.tf32.tf32.f32 "
        "{%0,%1,%2,%3}, {%4,%5,%6,%7}, {%8,%9}, {%0,%1,%2,%3};\n"
        : "+f"(d[0]), "+f"(d[1]), "+f"(d[2]), "+f"(d[3])
        : "r"(a0), "r"(a1), "r"(a2), "r"(a3), "r"(b0), "r"(b1));
}

// ---------------------------------------------------------------------------
// init: zero h (buffer 0) and c
// ---------------------------------------------------------------------------
__global__ void init_state() {
    int i = blockIdx.x * blockDim.x + threadIdx.x;
    if (i < BB * HH) {
        g_h[0][i] = 0.0f;
        g_c[i] = 0.0f;
    }
}

// ---------------------------------------------------------------------------
// pack_U: U[1024][4096] -> fragment layout [jb(128)][gate(4)][kk(128)][lane(32)] float2
// b0 = U[kk*8 + (lane&3)][gate*H + jb*8 + (lane>>2)], b1 = same with k+4. tf32-rounded.
// ---------------------------------------------------------------------------
__global__ __launch_bounds__(256) void pack_U(const float* __restrict__ U) {
    int idx = blockIdx.x * blockDim.x + threadIdx.x;  // 0 .. 2^21-1
    int lane = idx & 31;
    int kk   = (idx >> 5) & 127;
    int g    = (idx >> 12) & 3;
    int jb   = idx >> 14;
    int col  = g * HH + jb * 8 + (lane >> 2);
    int r0   = kk * 8 + (lane & 3);
    float u0 = U[(size_t)r0 * G4 + col];
    float u1 = U[(size_t)(r0 + 4) * G4 + col];
    uint32_t t0, t1;
    asm("cvt.rna.tf32.f32 %0, %1;" : "=r"(t0) : "f"(u0));
    asm("cvt.rna.tf32.f32 %0, %1;" : "=r"(t1) : "f"(u1));
    g_Upack[idx] = make_float2(__uint_as_float(t0), __uint_as_float(t1));
}

// ---------------------------------------------------------------------------
// GEMM1: xw[m][n] = sum_k E[ids[m]][k] * W[k][n] + bias[n]   (fp32, unchanged)
// ---------------------------------------------------------------------------
__global__ __launch_bounds__(256) void embed_gemm(
    const int* __restrict__ ids,
    const float* __restrict__ E,
    const float* __restrict__ W,
    const float* __restrict__ bias)
{
    __shared__ float As[8][132];
    __shared__ float Bs[8][128];
    __shared__ int ids_s[128];

    const int m0 = blockIdx.y * 128;
    const int n0 = blockIdx.x * 128;
    const int tid = threadIdx.x;

    if (tid < 128) ids_s[tid] = ids[m0 + tid];
    __syncthreads();

    const int tx = tid & 15;
    const int ty = tid >> 4;

    const int ar = tid >> 1;
    const int ak = (tid & 1) * 4;
    const int bk = tid >> 5;
    const int bc = (tid & 31) * 4;

    float acc[8][8];
#pragma unroll
    for (int i = 0; i < 8; i++)
#pragma unroll
        for (int j = 0; j < 8; j++) acc[i][j] = 0.0f;

    for (int k0 = 0; k0 < DD; k0 += 8) {
        float4 av = *(const float4*)&E[(size_t)ids_s[ar] * DD + k0 + ak];
        float4 bv = *(const float4*)&W[(size_t)(k0 + bk) * G4 + n0 + bc];

        __syncthreads();
        As[ak + 0][ar] = av.x;
        As[ak + 1][ar] = av.y;
        As[ak + 2][ar] = av.z;
        As[ak + 3][ar] = av.w;
        *(float4*)&Bs[bk][bc] = bv;
        __syncthreads();

#pragma unroll
        for (int k = 0; k < 8; k++) {
            float4 a0 = *(float4*)&As[k][ty * 4];
            float4 a1 = *(float4*)&As[k][64 + ty * 4];
            float4 b0 = *(float4*)&Bs[k][tx * 4];
            float4 b1 = *(float4*)&Bs[k][64 + tx * 4];
            float a[8] = {a0.x, a0.y, a0.z, a0.w, a1.x, a1.y, a1.z, a1.w};
            float b[8] = {b0.x, b0.y, b0.z, b0.w, b1.x, b1.y, b1.z, b1.w};
#pragma unroll
            for (int i = 0; i < 8; i++)
#pragma unroll
                for (int j = 0; j < 8; j++)
                    acc[i][j] = fmaf(a[i], b[j], acc[i][j]);
        }
    }

    float bval[8];
#pragma unroll
    for (int jj = 0; jj < 2; jj++) {
        float4 bv = *(const float4*)&bias[n0 + jj * 64 + tx * 4];
        bval[jj * 4 + 0] = bv.x; bval[jj * 4 + 1] = bv.y;
        bval[jj * 4 + 2] = bv.z; bval[jj * 4 + 3] = bv.w;
    }
#pragma unroll
    for (int ii = 0; ii < 2; ii++) {
#pragma unroll
        for (int i = 0; i < 4; i++) {
            int row = m0 + ii * 64 + ty * 4 + i;
#pragma unroll
            for (int jj = 0; jj < 2; jj++) {
                float4 v;
                v.x = acc[ii * 4 + i][jj * 4 + 0] + bval[jj * 4 + 0];
                v.y = acc[ii * 4 + i][jj * 4 + 1] + bval[jj * 4 + 1];
                v.z = acc[ii * 4 + i][jj * 4 + 2] + bval[jj * 4 + 2];
                v.w = acc[ii * 4 + i][jj * 4 + 3] + bval[jj * 4 + 3];
                *(float4*)&g_xw[(size_t)row * G4 + n0 + jj * 64 + tx * 4] = v;
            }
        }
    }
}

// ---------------------------------------------------------------------------
// One recurrence step (tensor-core tf32 mma). grid=128 blocks, 128 threads.
// Block owns 8 h-columns (j0 = blockIdx.x*8). Warp g computes gate g's 64x8
// z-slice via 4x m16n8k8 tiles over K=1024. Then gate fusion via smem exchange.
// ---------------------------------------------------------------------------
__global__ __launch_bounds__(128) void lstm_step_mma(
    const int* __restrict__ ids,
    float* __restrict__ outs,
    int t)
{
    const float* __restrict__ h_in = g_h[t & 1];
    float* __restrict__ h_out = g_h[(t + 1) & 1];

    // A fragments, packed: As4[kkl(16)][mt(4)][lane(32)] float4, lane XOR-swizzled by kkl&7
    __shared__ float4 As4[16][4][32];     // 32 KB
    __shared__ float  zs[4][64][8];       // 8 KB z-exchange

    const int tid  = threadIdx.x;
    const int warp = tid >> 5;            // = gate 0..3
    const int lane = tid & 31;
    const int j0   = blockIdx.x * 8;

    float d[4][4];                        // [mt][reg]
#pragma unroll
    for (int i = 0; i < 4; i++)
#pragma unroll
        for (int j = 0; j < 4; j++) d[i][j] = 0.0f;

    const float2* upbase =
        &g_Upack[(((size_t)blockIdx.x * 4 + warp) * 128) * 32 + lane];

#pragma unroll 1
    for (int chunk = 0; chunk < 8; chunk++) {
        const int k0 = chunk * 128;

        // Preload B fragments for this chunk (independent LDGs, overlap prev compute)
        float2 bfr[16];
        const float2* up = upbase + (size_t)(chunk * 16) * 32;
#pragma unroll
        for (int ki = 0; ki < 16; ki++) bfr[ki] = up[ki * 32];

        __syncthreads();  // everyone done reading previous As4

        // Stage h tile [64][128] into fragment-packed swizzled smem.
        // Warp-coalesced: each warp iteration covers one full h row (128 floats).
#pragma unroll
        for (int i = 0; i < 16; i++) {
            int idx = tid + i * 128;          // 0..2047
            int row = idx >> 5;               // 0..63
            int c4  = (idx & 31) * 4;         // 0..124
            float4 v = *(const float4*)&h_in[row * HH + k0 + c4];
            int mt  = row >> 4;
            int r16 = row & 15;
            int g8  = r16 & 7;
            int ahi = r16 >> 3;
            int kkl = c4 >> 3;
            int chi = (c4 >> 2) & 1;
            int slot = ahi + 2 * chi;
            float* base = (float*)&As4[kkl][mt][0];
            // element e -> lane (g8*4+e) XOR (kkl&7), same slot
            base[((g8 * 4 + 0) ^ (kkl & 7)) * 4 + slot] = v.x;
            base[((g8 * 4 + 1) ^ (kkl & 7)) * 4 + slot] = v.y;
            base[((g8 * 4 + 2) ^ (kkl & 7)) * 4 + slot] = v.z;
            base[((g8 * 4 + 3) ^ (kkl & 7)) * 4 + slot] = v.w;
        }
        __syncthreads();

        // Inner: 16 k-iters x 4 m-tiles of m16n8k8
#pragma unroll
        for (int ki = 0; ki < 16; ki++) {
            uint32_t b0 = __float_as_uint(bfr[ki].x);
            uint32_t b1 = __float_as_uint(bfr[ki].y);
            int ln = lane ^ (ki & 7);
#pragma unroll
            for (int mt = 0; mt < 4; mt++) {
                float4 a = As4[ki][mt][ln];
                mma_tf32(d[mt],
                         __float_as_uint(a.x), __float_as_uint(a.y),
                         __float_as_uint(a.z), __float_as_uint(a.w),
                         b0, b1);
            }
        }
    }

    // Write z fragments to exchange smem. d-frag layout:
    // c0:(r, 2c) c1:(r, 2c+1) c2:(r+8, 2c) c3:(r+8, 2c+1), r=lane>>2, c=lane&3
    {
        int r = lane >> 2;
        int c = (lane & 3) * 2;
#pragma unroll
        for (int mt = 0; mt < 4; mt++) {
            *(float2*)&zs[warp][mt * 16 + r][c]     = make_float2(d[mt][0], d[mt][1]);
            *(float2*)&zs[warp][mt * 16 + 8 + r][c] = make_float2(d[mt][2], d[mt][3]);
        }
    }
    __syncthreads();

    // Gate fusion: 512 (b, jj) items, 4 per thread
#pragma unroll
    for (int p = 0; p < 4; p++) {
        int idx = tid + p * 128;
        int jj = idx & 7;
        int b_ = idx >> 3;
        size_t xbase = ((size_t)(b_ * TT + t)) * G4 + j0 + jj;
        float zi = zs[0][b_][jj] + g_xw[xbase];
        float zf = zs[1][b_][jj] + g_xw[xbase + HH];
        float zg = zs[2][b_][jj] + g_xw[xbase + 2 * HH];
        float zo = zs[3][b_][jj] + g_xw[xbase + 3 * HH];

        float ig = sigf(zi);
        float fg = sigf(zf);
        float gg = sigf(zg);   // reference uses sigmoid here (not tanh)
        float og = sigf(zo);

        int hidx = b_ * HH + j0 + jj;
        float cold = g_c[hidx];
        float hold = h_in[hidx];

        float cn = fmaf(fg, cold, ig * gg);
        float hn = og * sigf(cn);  // reference: o * sigmoid(c_new)

        bool m = ids[b_ * TT + t] != 0;
        float hv = m ? hn : hold;
        float cv = m ? cn : cold;

        h_out[hidx] = hv;
        g_c[hidx] = cv;
        outs[((size_t)(b_ * TT + t)) * HH + j0 + jj] = hv;
    }
}

// ---------------------------------------------------------------------------
// finalize: append hF, cF after outs
// ---------------------------------------------------------------------------
__global__ void finalize(float* __restrict__ out) {
    int i = blockIdx.x * blockDim.x + threadIdx.x;
    if (i < BB * HH) {
        out[(size_t)BB * TT * HH + i] = g_h[0][i];   // h after t=511 is in buffer 0
        out[(size_t)BB * TT * HH + BB * HH + i] = g_c[i];
    }
}

extern "C" void kernel_launch(void* const* d_in, const int* in_sizes, int n_in,
                              void* d_out, int out_size) {
    const int*   ids  = (const int*)d_in[0];
    const float* E    = (const float*)d_in[1];
    const float* W    = (const float*)d_in[2];
    const float* U    = (const float*)d_in[3];
    const float* bias = (const float*)d_in[4];
    float* out = (float*)d_out;

    // 1. zero h0, c0; pack U into mma fragment layout (tf32)
    init_state<<<(BB * HH + 255) / 256, 256>>>();
    pack_U<<<8192, 256>>>(U);

    // 2. xw = E[ids] @ W + b   (fp32 SIMT)
    dim3 g1(G4 / 128, (BB * TT) / 128);
    embed_gemm<<<g1, 256>>>(ids, E, W, bias);

    // 3. 512 sequential recurrence steps (tensor-core tf32)
    for (int t = 0; t < TT; t++) {
        lstm_step_mma<<<HH / 8, 128>>>(ids, out, t);
    }

    // 4. append final h, c
    finalize<<<(BB * HH + 255) / 256, 256>>>(out);
}

// round 3
// speedup vs baseline: 2.5163x; 1.3379x over previous
#include <cuda_runtime.h>
#include <math.h>
#include <stdint.h>

#define BB 64
#define TT 512
#define VV 32000
#define DD 512
#define HH 1024
#define G4 4096  // 4*H
#define NBLK 128

// Scratch (allocation-free rule: __device__ globals only)
__device__ float  g_xw[(size_t)BB * TT * G4];   // 512 MB: xw = E[ids]@W + b
__device__ float  g_h[2][BB * HH];              // ping-pong hidden state
__device__ float2 g_Upack[128 * 4 * 128 * 32];  // 16 MB: U in mma-fragment layout (tf32)
__device__ unsigned g_count;                    // grid barrier arrive counter
__device__ unsigned g_release;                  // grid barrier release counter

__device__ __forceinline__ float sigf(float x) {
    return 1.0f / (1.0f + __expf(-x));
}

__device__ __forceinline__ void mma_tf32(float d[4],
                                         uint32_t a0, uint32_t a1, uint32_t a2, uint32_t a3,
                                         uint32_t b0, uint32_t b1) {
    asm volatile(
        "mma.sync.aligned.m16n8k8.row.col.f32.tf32.tf32.f32 "
        "{%0,%1,%2,%3}, {%4,%5,%6,%7}, {%8,%9}, {%0,%1,%2,%3};\n"
        : "+f"(d[0]), "+f"(d[1]), "+f"(d[2]), "+f"(d[3])
        : "r"(a0), "r"(a1), "r"(a2), "r"(a3), "r"(b0), "r"(b1));
}

__device__ __forceinline__ unsigned ld_acq(unsigned* p) {
    unsigned v;
    asm volatile("ld.acquire.gpu.u32 %0, [%1];" : "=r"(v) : "l"(p) : "memory");
    return v;
}

// ---------------------------------------------------------------------------
__global__ void reset_bar() { g_count = 0; g_release = 0; }

__global__ void init_state() {
    int i = blockIdx.x * blockDim.x + threadIdx.x;
    if (i < BB * HH) g_h[0][i] = 0.0f;
}

// ---------------------------------------------------------------------------
// pack_U: U[1024][4096] -> fragment layout [jb(128)][gate(4)][kk(128)][lane(32)]
// b0 = U[kk*8 + (lane&3)][gate*H + jb*8 + (lane>>2)], b1 same with k+4 (tf32)
// ---------------------------------------------------------------------------
__global__ __launch_bounds__(256) void pack_U(const float* __restrict__ U) {
    int idx = blockIdx.x * blockDim.x + threadIdx.x;
    int lane = idx & 31;
    int kk   = (idx >> 5) & 127;
    int g    = (idx >> 12) & 3;
    int jb   = idx >> 14;
    int col  = g * HH + jb * 8 + (lane >> 2);
    int r0   = kk * 8 + (lane & 3);
    float u0 = U[(size_t)r0 * G4 + col];
    float u1 = U[(size_t)(r0 + 4) * G4 + col];
    uint32_t t0, t1;
    asm("cvt.rna.tf32.f32 %0, %1;" : "=r"(t0) : "f"(u0));
    asm("cvt.rna.tf32.f32 %0, %1;" : "=r"(t1) : "f"(u1));
    g_Upack[idx] = make_float2(__uint_as_float(t0), __uint_as_float(t1));
}

// ---------------------------------------------------------------------------
// GEMM1: xw[m][n] = sum_k E[ids[m]][k] * W[k][n] + bias[n]   (fp32 SIMT)
// ---------------------------------------------------------------------------
__global__ __launch_bounds__(256) void embed_gemm(
    const int* __restrict__ ids,
    const float* __restrict__ E,
    const float* __restrict__ W,
    const float* __restrict__ bias)
{
    __shared__ float As[8][132];
    __shared__ float Bs[8][128];
    __shared__ int ids_s[128];

    const int m0 = blockIdx.y * 128;
    const int n0 = blockIdx.x * 128;
    const int tid = threadIdx.x;

    if (tid < 128) ids_s[tid] = ids[m0 + tid];
    __syncthreads();

    const int tx = tid & 15;
    const int ty = tid >> 4;
    const int ar = tid >> 1;
    const int ak = (tid & 1) * 4;
    const int bk = tid >> 5;
    const int bc = (tid & 31) * 4;

    float acc[8][8];
#pragma unroll
    for (int i = 0; i < 8; i++)
#pragma unroll
        for (int j = 0; j < 8; j++) acc[i][j] = 0.0f;

    for (int k0 = 0; k0 < DD; k0 += 8) {
        float4 av = *(const float4*)&E[(size_t)ids_s[ar] * DD + k0 + ak];
        float4 bv = *(const float4*)&W[(size_t)(k0 + bk) * G4 + n0 + bc];

        __syncthreads();
        As[ak + 0][ar] = av.x;
        As[ak + 1][ar] = av.y;
        As[ak + 2][ar] = av.z;
        As[ak + 3][ar] = av.w;
        *(float4*)&Bs[bk][bc] = bv;
        __syncthreads();

#pragma unroll
        for (int k = 0; k < 8; k++) {
            float4 a0 = *(float4*)&As[k][ty * 4];
            float4 a1 = *(float4*)&As[k][64 + ty * 4];
            float4 b0 = *(float4*)&Bs[k][tx * 4];
            float4 b1 = *(float4*)&Bs[k][64 + tx * 4];
            float a[8] = {a0.x, a0.y, a0.z, a0.w, a1.x, a1.y, a1.z, a1.w};
            float b[8] = {b0.x, b0.y, b0.z, b0.w, b1.x, b1.y, b1.z, b1.w};
#pragma unroll
            for (int i = 0; i < 8; i++)
#pragma unroll
                for (int j = 0; j < 8; j++)
                    acc[i][j] = fmaf(a[i], b[j], acc[i][j]);
        }
    }

    float bval[8];
#pragma unroll
    for (int jj = 0; jj < 2; jj++) {
        float4 bv = *(const float4*)&bias[n0 + jj * 64 + tx * 4];
        bval[jj * 4 + 0] = bv.x; bval[jj * 4 + 1] = bv.y;
        bval[jj * 4 + 2] = bv.z; bval[jj * 4 + 3] = bv.w;
    }
#pragma unroll
    for (int ii = 0; ii < 2; ii++) {
#pragma unroll
        for (int i = 0; i < 4; i++) {
            int row = m0 + ii * 64 + ty * 4 + i;
#pragma unroll
            for (int jj = 0; jj < 2; jj++) {
                float4 v;
                v.x = acc[ii * 4 + i][jj * 4 + 0] + bval[jj * 4 + 0];
                v.y = acc[ii * 4 + i][jj * 4 + 1] + bval[jj * 4 + 1];
                v.z = acc[ii * 4 + i][jj * 4 + 2] + bval[jj * 4 + 2];
                v.w = acc[ii * 4 + i][jj * 4 + 3] + bval[jj * 4 + 3];
                *(float4*)&g_xw[(size_t)row * G4 + n0 + jj * 64 + tx * 4] = v;
            }
        }
    }
}

// ---------------------------------------------------------------------------
// Persistent recurrence kernel. 128 blocks x 256 threads, all co-resident.
// Block jb owns 8 output columns (j0 = jb*8) = 32 z-columns across 4 gates.
// U slice (128 KB, tf32 fragment layout) loaded into smem ONCE.
// Per step: stage full h -> 2048 MMAs -> fused gates (c, own-h in registers)
// -> grid barrier.
// ---------------------------------------------------------------------------
__global__ __launch_bounds__(256, 1) void lstm_persist(
    const int* __restrict__ ids,
    float* __restrict__ out)
{
    extern __shared__ char smem_raw[];
    // layout: Us float2[4][128][32] (128 KB) | As4 float4[16][4][32] (32 KB) | zs float[4][64][8] (8 KB)
    float2 (*Us)[128][32] = (float2(*)[128][32])smem_raw;
    float4 (*As4)[4][32]  = (float4(*)[4][32])(smem_raw + 131072);
    float  (*zs)[64][8]   = (float(*)[64][8])(smem_raw + 131072 + 32768);

    const int tid  = threadIdx.x;
    const int warp = tid >> 5;
    const int lane = tid & 31;
    const int jb   = blockIdx.x;
    const int j0   = jb * 8;
    const int mt   = warp & 3;   // m-tile (16 rows each)
    const int nh   = warp >> 2;  // gate pair: gates {2nh, 2nh+1}

    // Load U slice into smem (once)
    {
        const float2* src = &g_Upack[(size_t)jb * 4 * 128 * 32];
        float2* dst = (float2*)smem_raw;
        for (int i = tid; i < 4 * 128 * 32; i += 256) dst[i] = src[i];
    }

    // Per-thread persistent state: 2 outputs (b_, jj) each
    float c_reg[2] = {0.0f, 0.0f};
    float h_reg[2] = {0.0f, 0.0f};
    int   bo[2], jo[2];
#pragma unroll
    for (int p = 0; p < 2; p++) {
        int idx = tid + p * 256;
        jo[p] = idx & 7;
        bo[p] = idx >> 3;
    }

    unsigned epoch = 0;
    __syncthreads();

#pragma unroll 1
    for (int t = 0; t < TT; t++) {
        const float* __restrict__ h_in = g_h[t & 1];
        float* __restrict__ h_out = g_h[(t + 1) & 1];

        // Prefetch xw for fusion (independent of h)
        float xwv[2][4];
#pragma unroll
        for (int p = 0; p < 2; p++) {
            size_t xbase = ((size_t)(bo[p] * TT + t)) * G4 + j0 + jo[p];
#pragma unroll
            for (int g = 0; g < 4; g++)
                xwv[p][g] = __ldcg(&g_xw[xbase + g * HH]);
        }

        float d[2][4];
#pragma unroll
        for (int i = 0; i < 2; i++)
#pragma unroll
            for (int j = 0; j < 4; j++) d[i][j] = 0.0f;

#pragma unroll 1
        for (int chunk = 0; chunk < 8; chunk++) {
            const int k0 = chunk * 128;

            __syncthreads();  // readers of As4 done
            // Stage h[64][k0..k0+128) into fragment-packed swizzled smem
#pragma unroll
            for (int i = 0; i < 8; i++) {
                int idx = tid + i * 256;          // 0..2047
                int row = idx >> 5;               // 0..63
                int c4  = (idx & 31) * 4;         // 0..124
                float4 v = __ldcv((const float4*)&h_in[row * HH + k0 + c4]);
                int mtt = row >> 4;
                int r16 = row & 15;
                int g8  = r16 & 7;
                int ahi = r16 >> 3;
                int kkl = c4 >> 3;
                int chi = (c4 >> 2) & 1;
                int slot = ahi + 2 * chi;
                float* base = (float*)&As4[kkl][mtt][0];
                base[((g8 * 4 + 0) ^ (kkl & 7)) * 4 + slot] = v.x;
                base[((g8 * 4 + 1) ^ (kkl & 7)) * 4 + slot] = v.y;
                base[((g8 * 4 + 2) ^ (kkl & 7)) * 4 + slot] = v.z;
                base[((g8 * 4 + 3) ^ (kkl & 7)) * 4 + slot] = v.w;
            }
            __syncthreads();

#pragma unroll
            for (int ki = 0; ki < 16; ki++) {
                int kg = chunk * 16 + ki;
                float4 a = As4[ki][mt][lane ^ (ki & 7)];
                uint32_t a0 = __float_as_uint(a.x), a1 = __float_as_uint(a.y);
                uint32_t a2 = __float_as_uint(a.z), a3 = __float_as_uint(a.w);
#pragma unroll
                for (int nt = 0; nt < 2; nt++) {
                    float2 b = Us[2 * nh + nt][kg][lane];
                    mma_tf32(d[nt], a0, a1, a2, a3,
                             __float_as_uint(b.x), __float_as_uint(b.y));
                }
            }
        }

        // z exchange
        {
            int r = lane >> 2;
            int c = (lane & 3) * 2;
#pragma unroll
            for (int nt = 0; nt < 2; nt++) {
                int g = 2 * nh + nt;
                *(float2*)&zs[g][mt * 16 + r][c]     = make_float2(d[nt][0], d[nt][1]);
                *(float2*)&zs[g][mt * 16 + 8 + r][c] = make_float2(d[nt][2], d[nt][3]);
            }
        }
        __syncthreads();

        // Gate fusion (c, own-h in registers)
#pragma unroll
        for (int p = 0; p < 2; p++) {
            int b_ = bo[p], jj = jo[p];
            float zi = zs[0][b_][jj] + xwv[p][0];
            float zf = zs[1][b_][jj] + xwv[p][1];
            float zg = zs[2][b_][jj] + xwv[p][2];
            float zo = zs[3][b_][jj] + xwv[p][3];

            float ig = sigf(zi);
            float fg = sigf(zf);
            float gg = sigf(zg);   // reference: sigmoid (not tanh)
            float og = sigf(zo);

            float cn = fmaf(fg, c_reg[p], ig * gg);
            float hn = og * sigf(cn);

            bool m = __ldg(&ids[b_ * TT + t]) != 0;
            float hv = m ? hn : h_reg[p];
            float cv = m ? cn : c_reg[p];

            h_reg[p] = hv;
            c_reg[p] = cv;

            int hidx = b_ * HH + j0 + jj;
            __stcg(&h_out[hidx], hv);
            __stcg(&out[((size_t)(b_ * TT + t)) * HH + j0 + jj], hv);
            if (t == TT - 1) {
                __stcg(&out[(size_t)BB * TT * HH + hidx], hv);
                __stcg(&out[(size_t)BB * TT * HH + BB * HH + hidx], cv);
            }
        }

        // Grid barrier
        __threadfence();
        __syncthreads();
        epoch++;
        if (tid == 0) {
            unsigned prev = atomicAdd(&g_count, 1);
            if (prev == NBLK - 1) {
                atomicExch(&g_count, 0);
                __threadfence();
                atomicAdd(&g_release, 1);
            } else {
                while (ld_acq(&g_release) < epoch) { }
            }
        }
        __syncthreads();
    }
}

extern "C" void kernel_launch(void* const* d_in, const int* in_sizes, int n_in,
                              void* d_out, int out_size) {
    const int*   ids  = (const int*)d_in[0];
    const float* E    = (const float*)d_in[1];
    const float* W    = (const float*)d_in[2];
    const float* U    = (const float*)d_in[3];
    const float* bias = (const float*)d_in[4];
    float* out = (float*)d_out;

    static bool attr_set = false;
    if (!attr_set) {
        cudaFuncSetAttribute(lstm_persist,
                             cudaFuncAttributeMaxDynamicSharedMemorySize, 172032);
        attr_set = true;
    }

    reset_bar<<<1, 1>>>();
    init_state<<<(BB * HH + 255) / 256, 256>>>();
    pack_U<<<8192, 256>>>(U);

    dim3 g1(G4 / 128, (BB * TT) / 128);
    embed_gemm<<<g1, 256>>>(ids, E, W, bias);

    lstm_persist<<<NBLK, 256, 172032>>>(ids, out);
}

// round 4
// speedup vs baseline: 3.4371x; 1.3659x over previous
#include <cuda_runtime.h>
#include <math.h>
#include <stdint.h>

#define BB 64
#define TT 512
#define VV 32000
#define DD 512
#define HH 1024
#define G4 4096  // 4*H
#define NBLK 128

// Scratch (allocation-free rule: __device__ globals only)
__device__ float  g_xw[(size_t)BB * TT * G4];   // 512 MB: xw = E[ids]@W + b
__device__ float  g_h[2][BB * HH];              // ping-pong hidden state
__device__ float2 g_Upack[128 * 4 * 128 * 32];  // 16 MB: U fragment layout (tf32)
__device__ float2 g_Wpack[512 * 64 * 32];       // 8 MB:  W fragment layout (tf32)
__device__ unsigned g_count;
__device__ unsigned g_release;

__device__ __forceinline__ float sigf(float x) {
    return 1.0f / (1.0f + __expf(-x));
}

__device__ __forceinline__ void mma_tf32(float d[4],
                                         uint32_t a0, uint32_t a1, uint32_t a2, uint32_t a3,
                                         uint32_t b0, uint32_t b1) {
    asm volatile(
        "mma.sync.aligned.m16n8k8.row.col.f32.tf32.tf32.f32 "
        "{%0,%1,%2,%3}, {%4,%5,%6,%7}, {%8,%9}, {%0,%1,%2,%3};\n"
        : "+f"(d[0]), "+f"(d[1]), "+f"(d[2]), "+f"(d[3])
        : "r"(a0), "r"(a1), "r"(a2), "r"(a3), "r"(b0), "r"(b1));
}

__device__ __forceinline__ void ldsm4(uint32_t& r0, uint32_t& r1, uint32_t& r2, uint32_t& r3,
                                      uint32_t saddr) {
    asm volatile("ldmatrix.sync.aligned.m8n8.x4.shared.b16 {%0,%1,%2,%3}, [%4];"
                 : "=r"(r0), "=r"(r1), "=r"(r2), "=r"(r3) : "r"(saddr));
}

__device__ __forceinline__ unsigned ld_acq(unsigned* p) {
    unsigned v;
    asm volatile("ld.acquire.gpu.u32 %0, [%1];" : "=r"(v) : "l"(p) : "memory");
    return v;
}

// ---------------------------------------------------------------------------
__global__ void reset_bar() { g_count = 0; g_release = 0; }

__global__ void init_state() {
    int i = blockIdx.x * blockDim.x + threadIdx.x;
    if (i < BB * HH) g_h[0][i] = 0.0f;
}

// ---------------------------------------------------------------------------
// pack_U: U[1024][4096] -> [jb(128)][gate(4)][kk(128)][lane(32)] float2 (tf32)
// b0 = U[kk*8 + (lane&3)][gate*H + jb*8 + (lane>>2)], b1 same with k+4
// ---------------------------------------------------------------------------
__global__ __launch_bounds__(256) void pack_U(const float* __restrict__ U) {
    int idx = blockIdx.x * blockDim.x + threadIdx.x;
    int lane = idx & 31;
    int kk   = (idx >> 5) & 127;
    int g    = (idx >> 12) & 3;
    int jb   = idx >> 14;
    int col  = g * HH + jb * 8 + (lane >> 2);
    int r0   = kk * 8 + (lane & 3);
    float u0 = U[(size_t)r0 * G4 + col];
    float u1 = U[(size_t)(r0 + 4) * G4 + col];
    uint32_t t0, t1;
    asm("cvt.rna.tf32.f32 %0, %1;" : "=r"(t0) : "f"(u0));
    asm("cvt.rna.tf32.f32 %0, %1;" : "=r"(t1) : "f"(u1));
    g_Upack[idx] = make_float2(__uint_as_float(t0), __uint_as_float(t1));
}

// ---------------------------------------------------------------------------
// pack_W: W[512][4096] -> [ntile(512)][kg(64)][lane(32)] float2 (tf32)
// b0 = W[kg*8 + (lane&3)][ntile*8 + (lane>>2)], b1 same with k+4
// ---------------------------------------------------------------------------
__global__ __launch_bounds__(256) void pack_W(const float* __restrict__ W) {
    int idx = blockIdx.x * blockDim.x + threadIdx.x;  // < 1048576
    int lane  = idx & 31;
    int kg    = (idx >> 5) & 63;
    int ntile = idx >> 11;
    int col = ntile * 8 + (lane >> 2);
    int r0  = kg * 8 + (lane & 3);
    float u0 = W[(size_t)r0 * G4 + col];
    float u1 = W[(size_t)(r0 + 4) * G4 + col];
    uint32_t t0, t1;
    asm("cvt.rna.tf32.f32 %0, %1;" : "=r"(t0) : "f"(u0));
    asm("cvt.rna.tf32.f32 %0, %1;" : "=r"(t1) : "f"(u1));
    g_Wpack[idx] = make_float2(__uint_as_float(t0), __uint_as_float(t1));
}

// ---------------------------------------------------------------------------
// embed GEMM (tf32 tensor): xw[m][n] = E[ids[m]] @ W + bias
// 128x128x32 block tiles, 256 thr, 8 warps (2m x 4n), warp = 64m x 32n.
// A: gathered E rows -> swizzled smem -> ldmatrix.x4. B: g_Wpack direct LDG.
// ---------------------------------------------------------------------------
__global__ __launch_bounds__(256, 1) void embed_gemm_tf32(
    const int* __restrict__ ids,
    const float* __restrict__ E,
    const float* __restrict__ bias)
{
    __shared__ int   ids_s[128];
    __shared__ float As[2][128][32];   // 32 KB, XOR-swizzled rows

    const int m0 = blockIdx.y * 128;
    const int n0 = blockIdx.x * 128;
    const int tid  = threadIdx.x;
    const int warp = tid >> 5;
    const int lane = tid & 31;
    const int mw   = warp >> 2;        // 0..1
    const int nw   = warp & 3;         // 0..3

    if (tid < 128) ids_s[tid] = ids[m0 + tid];
    __syncthreads();

    const int row7   = lane & 7;
    const int cghalf = (lane >> 4) & 1;
    const int rbase  = (lane & 7) + ((lane >> 3) & 1) * 8;

    // staging thread coords
    const int s_row = (tid >> 3) & 127;  // will recompute per i below
    (void)s_row;

    float d[4][4][4];
#pragma unroll
    for (int a = 0; a < 4; a++)
#pragma unroll
        for (int b = 0; b < 4; b++)
#pragma unroll
            for (int c = 0; c < 4; c++) d[a][b][c] = 0.0f;

    float4 va[4];
    // load + store chunk 0
#pragma unroll
    for (int i = 0; i < 4; i++) {
        int f4 = tid + i * 256;
        int row = f4 >> 3, cg = f4 & 7;
        va[i] = *(const float4*)&E[(size_t)ids_s[row] * DD + cg * 4];
    }
#pragma unroll
    for (int i = 0; i < 4; i++) {
        int f4 = tid + i * 256;
        int row = f4 >> 3, cg = f4 & 7;
        *(float4*)&As[0][row][(cg ^ (row & 7)) * 4] = va[i];
    }
    __syncthreads();

    const float2* wp = &g_Wpack[((size_t)(n0 >> 3) + nw * 4) * 64 * 32 + lane];

#pragma unroll 1
    for (int chunk = 0; chunk < 16; chunk++) {
        const int cur = chunk & 1;
        if (chunk < 15) {
            const int k0 = (chunk + 1) * 32;
#pragma unroll
            for (int i = 0; i < 4; i++) {
                int f4 = tid + i * 256;
                int row = f4 >> 3, cg = f4 & 7;
                va[i] = *(const float4*)&E[(size_t)ids_s[row] * DD + k0 + cg * 4];
            }
        }
        // B fragments for this chunk
        float2 bfr[4][4];
#pragma unroll
        for (int nt = 0; nt < 4; nt++)
#pragma unroll
            for (int ki = 0; ki < 4; ki++)
                bfr[nt][ki] = wp[(size_t)nt * 2048 + (chunk * 4 + ki) * 32];

        uint32_t abase = (uint32_t)__cvta_generic_to_shared(&As[cur][0][0]);
#pragma unroll
        for (int ki = 0; ki < 4; ki++) {
#pragma unroll
            for (int mt = 0; mt < 4; mt++) {
                int rowb = mw * 64 + mt * 16 + rbase;
                uint32_t a0, a1, a2, a3;
                ldsm4(a0, a1, a2, a3,
                      abase + rowb * 128 + (((2 * ki + cghalf) ^ row7) << 4));
#pragma unroll
                for (int nt = 0; nt < 4; nt++)
                    mma_tf32(d[mt][nt], a0, a1, a2, a3,
                             __float_as_uint(bfr[nt][ki].x),
                             __float_as_uint(bfr[nt][ki].y));
            }
        }
        if (chunk < 15) {
#pragma unroll
            for (int i = 0; i < 4; i++) {
                int f4 = tid + i * 256;
                int row = f4 >> 3, cg = f4 & 7;
                *(float4*)&As[cur ^ 1][row][(cg ^ (row & 7)) * 4] = va[i];
            }
        }
        __syncthreads();
    }

    // epilogue: + bias, write g_xw
    const int rr = lane >> 2;
    const int cc = (lane & 3) * 2;
#pragma unroll
    for (int nt = 0; nt < 4; nt++) {
        int col = n0 + nw * 32 + nt * 8 + cc;
        float2 bv = *(const float2*)&bias[col];
#pragma unroll
        for (int mt = 0; mt < 4; mt++) {
            int row = m0 + mw * 64 + mt * 16 + rr;
            float2 v0 = make_float2(d[mt][nt][0] + bv.x, d[mt][nt][1] + bv.y);
            float2 v1 = make_float2(d[mt][nt][2] + bv.x, d[mt][nt][3] + bv.y);
            *(float2*)&g_xw[(size_t)row * G4 + col] = v0;
            *(float2*)&g_xw[(size_t)(row + 8) * G4 + col] = v1;
        }
    }
}

// ---------------------------------------------------------------------------
// Persistent recurrence. 128 blocks x 256 thr. Block jb owns 8 h-cols.
// U slice (128 KB) in smem once. Per step: double-buffered h staging
// (row-swizzled, ldmatrix) -> 2048 tf32 MMAs -> fused gates -> grid barrier.
// ---------------------------------------------------------------------------
__global__ __launch_bounds__(256, 1) void lstm_persist(
    const int* __restrict__ ids,
    float* __restrict__ out)
{
    extern __shared__ char smem_raw[];
    float2 (*Us)[128][32] = (float2(*)[128][32])smem_raw;                    // 128 KB
    float  (*As)[64][128] = (float(*)[64][128])(smem_raw + 131072);          // 64 KB (x2)
    float  (*zs)[64][8]   = (float(*)[64][8])(smem_raw + 131072 + 65536);    // 8 KB

    const int tid  = threadIdx.x;
    const int warp = tid >> 5;
    const int lane = tid & 31;
    const int jb   = blockIdx.x;
    const int j0   = jb * 8;
    const int mt   = warp & 3;   // m-tile (16 rows)
    const int nh   = warp >> 2;  // gate pair {2nh, 2nh+1}

    // Load U slice once
    {
        const float2* src = &g_Upack[(size_t)jb * 4 * 128 * 32];
        float2* dst = (float2*)smem_raw;
        for (int i = tid; i < 4 * 128 * 32; i += 256) dst[i] = src[i];
    }

    // ldmatrix per-thread constants
    const int row7    = lane & 7;
    const int rowbase = mt * 16 + (lane & 7) + ((lane >> 3) & 1) * 8;
    const int cghalf  = (lane >> 4) & 1;

    // persistent per-thread state: 2 outputs each
    float c_reg[2] = {0.0f, 0.0f};
    float h_reg[2] = {0.0f, 0.0f};
    int bo[2], jo[2];
#pragma unroll
    for (int p = 0; p < 2; p++) {
        int idx = tid + p * 256;
        jo[p] = idx & 7;
        bo[p] = idx >> 3;
    }

    unsigned epoch = 0;
    __syncthreads();

#pragma unroll 1
    for (int t = 0; t < TT; t++) {
        const float* __restrict__ h_in = g_h[t & 1];
        float* __restrict__ h_out = g_h[(t + 1) & 1];

        // prefetch xw
        float xwv[2][4];
#pragma unroll
        for (int p = 0; p < 2; p++) {
            size_t xbase = ((size_t)(bo[p] * TT + t)) * G4 + j0 + jo[p];
#pragma unroll
            for (int g = 0; g < 4; g++)
                xwv[p][g] = __ldcg(&g_xw[xbase + g * HH]);
        }

        float d[2][4];
#pragma unroll
        for (int i = 0; i < 2; i++)
#pragma unroll
            for (int j = 0; j < 4; j++) d[i][j] = 0.0f;

        float4 va[8];
        // stage chunk 0
#pragma unroll
        for (int i = 0; i < 8; i++) {
            int f4 = tid + i * 256;
            int row = f4 >> 5, cg = f4 & 31;
            va[i] = __ldcv((const float4*)&h_in[row * HH + cg * 4]);
        }
#pragma unroll
        for (int i = 0; i < 8; i++) {
            int f4 = tid + i * 256;
            int row = f4 >> 5, cg = f4 & 31;
            *(float4*)&As[0][row][(cg ^ (row & 7)) * 4] = va[i];
        }
        __syncthreads();

#pragma unroll 1
        for (int chunk = 0; chunk < 8; chunk++) {
            const int cur = chunk & 1;
            if (chunk < 7) {
                const int k0 = (chunk + 1) * 128;
#pragma unroll
                for (int i = 0; i < 8; i++) {
                    int f4 = tid + i * 256;
                    int row = f4 >> 5, cg = f4 & 31;
                    va[i] = __ldcv((const float4*)&h_in[row * HH + k0 + cg * 4]);
                }
            }
            uint32_t abase = (uint32_t)__cvta_generic_to_shared(&As[cur][0][0])
                             + rowbase * 512;
#pragma unroll
            for (int ki = 0; ki < 16; ki++) {
                int kg = chunk * 16 + ki;
                uint32_t a0, a1, a2, a3;
                ldsm4(a0, a1, a2, a3, abase + (((2 * ki + cghalf) ^ row7) << 4));
#pragma unroll
                for (int nt = 0; nt < 2; nt++) {
                    float2 b = Us[2 * nh + nt][kg][lane];
                    mma_tf32(d[nt], a0, a1, a2, a3,
                             __float_as_uint(b.x), __float_as_uint(b.y));
                }
            }
            if (chunk < 7) {
#pragma unroll
                for (int i = 0; i < 8; i++) {
                    int f4 = tid + i * 256;
                    int row = f4 >> 5, cg = f4 & 31;
                    *(float4*)&As[cur ^ 1][row][(cg ^ (row & 7)) * 4] = va[i];
                }
            }
            __syncthreads();
        }

        // z exchange
        {
            int r = lane >> 2;
            int c = (lane & 3) * 2;
#pragma unroll
            for (int nt = 0; nt < 2; nt++) {
                int g = 2 * nh + nt;
                *(float2*)&zs[g][mt * 16 + r][c]     = make_float2(d[nt][0], d[nt][1]);
                *(float2*)&zs[g][mt * 16 + 8 + r][c] = make_float2(d[nt][2], d[nt][3]);
            }
        }
        __syncthreads();

        // gate fusion
#pragma unroll
        for (int p = 0; p < 2; p++) {
            int b_ = bo[p], jj = jo[p];
            float zi = zs[0][b_][jj] + xwv[p][0];
            float zf = zs[1][b_][jj] + xwv[p][1];
            float zg = zs[2][b_][jj] + xwv[p][2];
            float zo = zs[3][b_][jj] + xwv[p][3];

            float ig = sigf(zi);
            float fg = sigf(zf);
            float gg = sigf(zg);   // reference: sigmoid (not tanh)
            float og = sigf(zo);

            float cn = fmaf(fg, c_reg[p], ig * gg);
            float hn = og * sigf(cn);

            bool m = __ldg(&ids[b_ * TT + t]) != 0;
            float hv = m ? hn : h_reg[p];
            float cv = m ? cn : c_reg[p];

            h_reg[p] = hv;
            c_reg[p] = cv;

            int hidx = b_ * HH + j0 + jj;
            __stcg(&h_out[hidx], hv);
            __stcg(&out[((size_t)(b_ * TT + t)) * HH + j0 + jj], hv);
            if (t == TT - 1) {
                __stcg(&out[(size_t)BB * TT * HH + hidx], hv);
                __stcg(&out[(size_t)BB * TT * HH + BB * HH + hidx], cv);
            }
        }

        // grid barrier
        __threadfence();
        __syncthreads();
        epoch++;
        if (tid == 0) {
            unsigned prev = atomicAdd(&g_count, 1);
            if (prev == NBLK - 1) {
                atomicExch(&g_count, 0);
                __threadfence();
                atomicAdd(&g_release, 1);
            } else {
                while (ld_acq(&g_release) < epoch) { }
            }
        }
        __syncthreads();
    }
}

extern "C" void kernel_launch(void* const* d_in, const int* in_sizes, int n_in,
                              void* d_out, int out_size) {
    const int*   ids  = (const int*)d_in[0];
    const float* E    = (const float*)d_in[1];
    const float* W    = (const float*)d_in[2];
    const float* U    = (const float*)d_in[3];
    const float* bias = (const float*)d_in[4];
    float* out = (float*)d_out;

    static bool attr_set = false;
    if (!attr_set) {
        cudaFuncSetAttribute(lstm_persist,
                             cudaFuncAttributeMaxDynamicSharedMemorySize, 204800);
        attr_set = true;
    }

    reset_bar<<<1, 1>>>();
    init_state<<<(BB * HH + 255) / 256, 256>>>();
    pack_U<<<8192, 256>>>(U);
    pack_W<<<4096, 256>>>(W);

    dim3 g1(G4 / 128, (BB * TT) / 128);  // (32, 256)
    embed_gemm_tf32<<<g1, 256>>>(ids, E, bias);

    lstm_persist<<<NBLK, 256, 204800>>>(ids, out);
}

// round 6
// speedup vs baseline: 3.7406x; 1.0883x over previous
#include <cuda_runtime.h>
#include <cuda_fp16.h>
#include <math.h>
#include <stdint.h>

#define BB 64
#define TT 512
#define DD 512
#define HH 1024
#define G4 4096  // 4*H
#define NBLK 128

// Scratch (allocation-free rule: __device__ globals only)
__device__ float    g_xw[(size_t)BB * TT * G4];   // 512 MB
__device__ uint4    g_h4[2][BB * HH / 8];         // ping-pong hidden state (fp16, 8/uint4)
__device__ uint2    g_Uh[128 * 4 * 64 * 32];      // 8 MB: U fp16 fragment layout
__device__ float2   g_Wpack[512 * 64 * 32];       // 8 MB: W tf32 fragment layout (embed)
__device__ unsigned g_arrive[NBLK];
__device__ unsigned g_rel;

__device__ __forceinline__ float sigf(float x) {
    return 1.0f / (1.0f + __expf(-x));
}

__device__ __forceinline__ void mma_tf32(float d[4],
                                         uint32_t a0, uint32_t a1, uint32_t a2, uint32_t a3,
                                         uint32_t b0, uint32_t b1) {
    asm volatile(
        "mma.sync.aligned.m16n8k8.row.col.f32.tf32.tf32.f32 "
        "{%0,%1,%2,%3}, {%4,%5,%6,%7}, {%8,%9}, {%0,%1,%2,%3};\n"
        : "+f"(d[0]), "+f"(d[1]), "+f"(d[2]), "+f"(d[3])
        : "r"(a0), "r"(a1), "r"(a2), "r"(a3), "r"(b0), "r"(b1));
}

__device__ __forceinline__ void mma_f16(float d[4],
                                        uint32_t a0, uint32_t a1, uint32_t a2, uint32_t a3,
                                        uint32_t b0, uint32_t b1) {
    asm volatile(
        "mma.sync.aligned.m16n8k16.row.col.f32.f16.f16.f32 "
        "{%0,%1,%2,%3}, {%4,%5,%6,%7}, {%8,%9}, {%0,%1,%2,%3};\n"
        : "+f"(d[0]), "+f"(d[1]), "+f"(d[2]), "+f"(d[3])
        : "r"(a0), "r"(a1), "r"(a2), "r"(a3), "r"(b0), "r"(b1));
}

__device__ __forceinline__ void ldsm4(uint32_t& r0, uint32_t& r1, uint32_t& r2, uint32_t& r3,
                                      uint32_t saddr) {
    asm volatile("ldmatrix.sync.aligned.m8n8.x4.shared.b16 {%0,%1,%2,%3}, [%4];"
                 : "=r"(r0), "=r"(r1), "=r"(r2), "=r"(r3) : "r"(saddr));
}

__device__ __forceinline__ unsigned ld_acq(unsigned* p) {
    unsigned v;
    asm volatile("ld.acquire.gpu.u32 %0, [%1];" : "=r"(v) : "l"(p) : "memory");
    return v;
}

__device__ __forceinline__ void st_rel(unsigned* p, unsigned v) {
    asm volatile("st.release.gpu.u32 [%0], %1;" :: "l"(p), "r"(v) : "memory");
}

__device__ __forceinline__ uint32_t smem_u32(const void* p) {
    uint32_t a;
    asm("{ .reg .u64 t; cvta.to.shared.u64 t, %1; cvt.u32.u64 %0, t; }" : "=r"(a) : "l"(p));
    return a;
}

// ---------------------------------------------------------------------------
__global__ void reset_bar() {
    if (threadIdx.x < NBLK) g_arrive[threadIdx.x] = 0;
    if (threadIdx.x == 0) g_rel = 0;
}

__global__ void init_state() {
    int i = blockIdx.x * blockDim.x + threadIdx.x;
    if (i < BB * HH / 8) g_h4[0][i] = make_uint4(0, 0, 0, 0);
}

// ---------------------------------------------------------------------------
// pack_Uh: U[1024][4096] -> [jb(128)][gate(4)][k16(64)][lane(32)] uint2 (fp16)
// b0 = {U[k16*16 + 2*(lane&3)][col], U[..+1][col]}, b1 = same rows +8
// col = gate*H + jb*8 + (lane>>2)
// ---------------------------------------------------------------------------
__global__ __launch_bounds__(256) void pack_Uh(const float* __restrict__ U) {
    int idx = blockIdx.x * blockDim.x + threadIdx.x;  // < 1048576
    int lane = idx & 31;
    int k16  = (idx >> 5) & 63;
    int gate = (idx >> 11) & 3;
    int jb   = idx >> 13;
    int col = gate * HH + jb * 8 + (lane >> 2);
    int r0  = k16 * 16 + (lane & 3) * 2;
    float u00 = U[(size_t)r0 * G4 + col];
    float u01 = U[(size_t)(r0 + 1) * G4 + col];
    float u10 = U[(size_t)(r0 + 8) * G4 + col];
    float u11 = U[(size_t)(r0 + 9) * G4 + col];
    __half2 h0 = __floats2half2_rn(u00, u01);
    __half2 h1 = __floats2half2_rn(u10, u11);
    uint2 v;
    v.x = *(uint32_t*)&h0;
    v.y = *(uint32_t*)&h1;
    g_Uh[idx] = v;
}

// ---------------------------------------------------------------------------
// pack_W: W[512][4096] -> [ntile(512)][kg(64)][lane(32)] float2 (tf32) for embed
// ---------------------------------------------------------------------------
__global__ __launch_bounds__(256) void pack_W(const float* __restrict__ W) {
    int idx = blockIdx.x * blockDim.x + threadIdx.x;
    int lane  = idx & 31;
    int kg    = (idx >> 5) & 63;
    int ntile = idx >> 11;
    int col = ntile * 8 + (lane >> 2);
    int r0  = kg * 8 + (lane & 3);
    float u0 = W[(size_t)r0 * G4 + col];
    float u1 = W[(size_t)(r0 + 4) * G4 + col];
    uint32_t t0, t1;
    asm("cvt.rna.tf32.f32 %0, %1;" : "=r"(t0) : "f"(u0));
    asm("cvt.rna.tf32.f32 %0, %1;" : "=r"(t1) : "f"(u1));
    g_Wpack[idx] = make_float2(__uint_as_float(t0), __uint_as_float(t1));
}

// ---------------------------------------------------------------------------
// embed GEMM (tf32 mma.sync): xw = E[ids] @ W + bias   (proven, unchanged)
// ---------------------------------------------------------------------------
__global__ __launch_bounds__(256, 1) void embed_gemm_tf32(
    const int* __restrict__ ids,
    const float* __restrict__ E,
    const float* __restrict__ bias)
{
    __shared__ int   ids_s[128];
    __shared__ float As[2][128][32];

    const int m0 = blockIdx.y * 128;
    const int n0 = blockIdx.x * 128;
    const int tid  = threadIdx.x;
    const int warp = tid >> 5;
    const int lane = tid & 31;
    const int mw   = warp >> 2;
    const int nw   = warp & 3;

    if (tid < 128) ids_s[tid] = ids[m0 + tid];
    __syncthreads();

    const int row7   = lane & 7;
    const int cghalf = (lane >> 4) & 1;
    const int rbase  = (lane & 7) + ((lane >> 3) & 1) * 8;

    float d[4][4][4];
#pragma unroll
    for (int a = 0; a < 4; a++)
#pragma unroll
        for (int b = 0; b < 4; b++)
#pragma unroll
            for (int c = 0; c < 4; c++) d[a][b][c] = 0.0f;

    float4 va[4];
#pragma unroll
    for (int i = 0; i < 4; i++) {
        int f4 = tid + i * 256;
        int row = f4 >> 3, cg = f4 & 7;
        va[i] = *(const float4*)&E[(size_t)ids_s[row] * DD + cg * 4];
    }
#pragma unroll
    for (int i = 0; i < 4; i++) {
        int f4 = tid + i * 256;
        int row = f4 >> 3, cg = f4 & 7;
        *(float4*)&As[0][row][(cg ^ (row & 7)) * 4] = va[i];
    }
    __syncthreads();

    const float2* wp = &g_Wpack[((size_t)(n0 >> 3) + nw * 4) * 64 * 32 + lane];

#pragma unroll 1
    for (int chunk = 0; chunk < 16; chunk++) {
        const int cur = chunk & 1;
        if (chunk < 15) {
            const int k0 = (chunk + 1) * 32;
#pragma unroll
            for (int i = 0; i < 4; i++) {
                int f4 = tid + i * 256;
                int row = f4 >> 3, cg = f4 & 7;
                va[i] = *(const float4*)&E[(size_t)ids_s[row] * DD + k0 + cg * 4];
            }
        }
        float2 bfr[4][4];
#pragma unroll
        for (int nt = 0; nt < 4; nt++)
#pragma unroll
            for (int ki = 0; ki < 4; ki++)
                bfr[nt][ki] = wp[(size_t)nt * 2048 + (chunk * 4 + ki) * 32];

        uint32_t abase = (uint32_t)__cvta_generic_to_shared(&As[cur][0][0]);
#pragma unroll
        for (int ki = 0; ki < 4; ki++) {
#pragma unroll
            for (int mt = 0; mt < 4; mt++) {
                int rowb = mw * 64 + mt * 16 + rbase;
                uint32_t a0, a1, a2, a3;
                ldsm4(a0, a1, a2, a3,
                      abase + rowb * 128 + (((2 * ki + cghalf) ^ row7) << 4));
#pragma unroll
                for (int nt = 0; nt < 4; nt++)
                    mma_tf32(d[mt][nt], a0, a1, a2, a3,
                             __float_as_uint(bfr[nt][ki].x),
                             __float_as_uint(bfr[nt][ki].y));
            }
        }
        if (chunk < 15) {
#pragma unroll
            for (int i = 0; i < 4; i++) {
                int f4 = tid + i * 256;
                int row = f4 >> 3, cg = f4 & 7;
                *(float4*)&As[cur ^ 1][row][(cg ^ (row & 7)) * 4] = va[i];
            }
        }
        __syncthreads();
    }

    const int rr = lane >> 2;
    const int cc = (lane & 3) * 2;
#pragma unroll
    for (int nt = 0; nt < 4; nt++) {
        int col = n0 + nw * 32 + nt * 8 + cc;
        float2 bv = *(const float2*)&bias[col];
#pragma unroll
        for (int mt = 0; mt < 4; mt++) {
            int row = m0 + mw * 64 + mt * 16 + rr;
            float2 v0 = make_float2(d[mt][nt][0] + bv.x, d[mt][nt][1] + bv.y);
            float2 v1 = make_float2(d[mt][nt][2] + bv.x, d[mt][nt][3] + bv.y);
            *(float2*)&g_xw[(size_t)row * G4 + col] = v0;
            *(float2*)&g_xw[(size_t)(row + 8) * G4 + col] = v1;
        }
    }
}

// ---------------------------------------------------------------------------
// Persistent recurrence (fp16 m16n8k16). 128 blocks x 256 thr, 1 block/SM.
// Block jb owns 8 h-cols. Warp (mt, nh): m-tile mt (16 rows), gate pair nh.
// U slice (64 KB fp16 fragments) in smem once. h ping-pong stored fp16.
// SMEM: Us 64KB @0 | A bufs 2x16KB @65536 | zs 4x64x9 floats @98304
// ---------------------------------------------------------------------------
__global__ __launch_bounds__(256, 1) void lstm_persist(
    const int* __restrict__ ids,
    float* __restrict__ out)
{
    extern __shared__ char smem_raw[];
    const uint32_t sbase = smem_u32(smem_raw);
    uint2* Us   = (uint2*)smem_raw;                         // [4][64][32]
    float* zsp  = (float*)(smem_raw + 98304);               // [4][64][9]

    const int tid  = threadIdx.x;
    const int warp = tid >> 5;
    const int lane = tid & 31;
    const int jb   = blockIdx.x;
    const int j0   = jb * 8;
    const int mt   = warp & 3;
    const int nh   = warp >> 2;

    // Load U slice once (64 KB)
    {
        const uint4* src = (const uint4*)&g_Uh[(size_t)jb * 4 * 64 * 32];
        uint4* dst = (uint4*)smem_raw;
        for (int i = tid; i < 4096; i += 256) dst[i] = src[i];
    }

    // ldmatrix constants
    const int rowbase = mt * 16 + (lane & 7) + ((lane >> 3) & 1) * 8;
    const int row7    = rowbase & 7;
    const int kh      = (lane >> 4) & 1;

    // persistent per-thread state (warps 0-1): row b = warp*32+lane, 8 cols
    const int brow = warp * 32 + lane;
    float c_reg[8], h_reg[8];
#pragma unroll
    for (int i = 0; i < 8; i++) { c_reg[i] = 0.0f; h_reg[i] = 0.0f; }

    const uint2* Ug0 = Us + (2 * nh + 0) * 64 * 32 + lane;
    const uint2* Ug1 = Us + (2 * nh + 1) * 64 * 32 + lane;

    __syncthreads();

#pragma unroll 1
    for (int t = 0; t < TT; t++) {
        const uint4* __restrict__ hin = g_h4[t & 1];
        uint4* __restrict__ hout = g_h4[(t + 1) & 1];

        // prefetch xw + mask (warps 0-1 meaningful)
        float4 xw0[4], xw1[4];
        bool msk = false;
        if (warp < 2) {
            const float* xb = &g_xw[((size_t)(brow * TT + t)) * G4 + j0];
#pragma unroll
            for (int g = 0; g < 4; g++) {
                xw0[g] = __ldcg((const float4*)&xb[g * HH]);
                xw1[g] = __ldcg((const float4*)&xb[g * HH + 4]);
            }
            msk = __ldg(&ids[brow * TT + t]) != 0;
        }

        float d[2][4];
#pragma unroll
        for (int i = 0; i < 2; i++)
#pragma unroll
            for (int j = 0; j < 4; j++) d[i][j] = 0.0f;

        // stage chunk 0: 1024 16B-units (64 rows x 16 units of 8 fp16)
        uint4 va[4];
#pragma unroll
        for (int i = 0; i < 4; i++) {
            int ul = tid + i * 256;
            int row = ul >> 4, u = ul & 15;
            va[i] = __ldcv(&hin[row * 128 + u]);
        }
#pragma unroll
        for (int i = 0; i < 4; i++) {
            int ul = tid + i * 256;
            int row = ul >> 4, u = ul & 15;
            *(uint4*)(smem_raw + 65536 + row * 256 + ((u ^ (row & 7)) << 4)) = va[i];
        }
        __syncthreads();

#pragma unroll 1
        for (int c = 0; c < 8; c++) {
            const int cur = c & 1;
            if (c < 7) {
                const int kq = (c + 1) * 16;  // uint4 offset of next chunk
#pragma unroll
                for (int i = 0; i < 4; i++) {
                    int ul = tid + i * 256;
                    int row = ul >> 4, u = ul & 15;
                    va[i] = __ldcv(&hin[row * 128 + kq + u]);
                }
            }
            uint32_t abase = sbase + 65536 + cur * 16384 + rowbase * 256;
#pragma unroll
            for (int ki = 0; ki < 8; ki++) {
                uint32_t a0, a1, a2, a3;
                ldsm4(a0, a1, a2, a3, abase + (((2 * ki + kh) ^ row7) << 4));
                uint2 b0 = Ug0[(c * 8 + ki) * 32];
                uint2 b1 = Ug1[(c * 8 + ki) * 32];
                mma_f16(d[0], a0, a1, a2, a3, b0.x, b0.y);
                mma_f16(d[1], a0, a1, a2, a3, b1.x, b1.y);
            }
            if (c < 7) {
#pragma unroll
                for (int i = 0; i < 4; i++) {
                    int ul = tid + i * 256;
                    int row = ul >> 4, u = ul & 15;
                    *(uint4*)(smem_raw + 65536 + (cur ^ 1) * 16384 + row * 256
                              + ((u ^ (row & 7)) << 4)) = va[i];
                }
            }
            __syncthreads();
        }

        // z exchange (rows padded to 9 floats)
        {
            int r = lane >> 2;
            int c2 = (lane & 3) * 2;
#pragma unroll
            for (int nt = 0; nt < 2; nt++) {
                int g = 2 * nh + nt;
                float* zr = zsp + g * 576;
                zr[(mt * 16 + r) * 9 + c2]     = d[nt][0];
                zr[(mt * 16 + r) * 9 + c2 + 1] = d[nt][1];
                zr[(mt * 16 + 8 + r) * 9 + c2]     = d[nt][2];
                zr[(mt * 16 + 8 + r) * 9 + c2 + 1] = d[nt][3];
            }
        }
        __syncthreads();

        // gate fusion (warps 0-1)
        if (warp < 2) {
            float hv[8], cv[8];
            const float* xi = (const float*)xw0;
            const float* xj = (const float*)xw1;
#pragma unroll
            for (int jj = 0; jj < 8; jj++) {
                float xv0 = (jj < 4) ? xi[0 * 4 + jj] : xj[0 * 4 + jj - 4];
                float xv1 = (jj < 4) ? xi[1 * 4 + jj] : xj[1 * 4 + jj - 4];
                float xv2 = (jj < 4) ? xi[2 * 4 + jj] : xj[2 * 4 + jj - 4];
                float xv3 = (jj < 4) ? xi[3 * 4 + jj] : xj[3 * 4 + jj - 4];
                float zi = zsp[0 * 576 + brow * 9 + jj] + xv0;
                float zf = zsp[1 * 576 + brow * 9 + jj] + xv1;
                float zg = zsp[2 * 576 + brow * 9 + jj] + xv2;
                float zo = zsp[3 * 576 + brow * 9 + jj] + xv3;

                float ig = sigf(zi);
                float fg = sigf(zf);
                float gg = sigf(zg);   // reference: sigmoid (not tanh)
                float og = sigf(zo);

                float cn = fmaf(fg, c_reg[jj], ig * gg);
                float hn = og * sigf(cn);

                hv[jj] = msk ? hn : h_reg[jj];
                cv[jj] = msk ? cn : c_reg[jj];
                h_reg[jj] = hv[jj];
                c_reg[jj] = cv[jj];
            }
            // h_out: 8 fp16 = one uint4
            __half2 p0 = __floats2half2_rn(hv[0], hv[1]);
            __half2 p1 = __floats2half2_rn(hv[2], hv[3]);
            __half2 p2 = __floats2half2_rn(hv[4], hv[5]);
            __half2 p3 = __floats2half2_rn(hv[6], hv[7]);
            uint4 hh;
            hh.x = *(uint32_t*)&p0; hh.y = *(uint32_t*)&p1;
            hh.z = *(uint32_t*)&p2; hh.w = *(uint32_t*)&p3;
            __stcg(&hout[brow * 128 + jb], hh);

            float4* op = (float4*)&out[((size_t)(brow * TT + t)) * HH + j0];
            __stcg(&op[0], make_float4(hv[0], hv[1], hv[2], hv[3]));
            __stcg(&op[1], make_float4(hv[4], hv[5], hv[6], hv[7]));
            if (t == TT - 1) {
                float4* fp = (float4*)&out[(size_t)BB * TT * HH + brow * HH + j0];
                __stcg(&fp[0], make_float4(hv[0], hv[1], hv[2], hv[3]));
                __stcg(&fp[1], make_float4(hv[4], hv[5], hv[6], hv[7]));
                float4* cp = (float4*)&out[(size_t)BB * TT * HH + BB * HH + brow * HH + j0];
                __stcg(&cp[0], make_float4(cv[0], cv[1], cv[2], cv[3]));
                __stcg(&cp[1], make_float4(cv[4], cv[5], cv[6], cv[7]));
            }
        }

        // grid barrier: flag-based (no serialized atomics)
        __syncthreads();
        unsigned e = (unsigned)t + 1;
        if (blockIdx.x == 0) {
            if (tid == 0) {
                __threadfence();
                st_rel(&g_arrive[0], e);
            }
            if (tid < NBLK) {
                while (ld_acq(&g_arrive[tid]) < e) { }
            }
            __syncthreads();
            if (tid == 0) st_rel(&g_rel, e);
        } else {
            if (tid == 0) {
                __threadfence();
                st_rel(&g_arrive[blockIdx.x], e);
                while (ld_acq(&g_rel) < e) { }
            }
            __syncthreads();
        }
    }
}

extern "C" void kernel_launch(void* const* d_in, const int* in_sizes, int n_in,
                              void* d_out, int out_size) {
    const int*   ids  = (const int*)d_in[0];
    const float* E    = (const float*)d_in[1];
    const float* W    = (const float*)d_in[2];
    const float* U    = (const float*)d_in[3];
    const float* bias = (const float*)d_in[4];
    float* out = (float*)d_out;

    static bool attr_set = false;
    if (!attr_set) {
        cudaFuncSetAttribute(lstm_persist,
                             cudaFuncAttributeMaxDynamicSharedMemorySize, 107520);
        attr_set = true;
    }

    reset_bar<<<1, 128>>>();
    init_state<<<(BB * HH / 8 + 255) / 256, 256>>>();
    pack_Uh<<<4096, 256>>>(U);
    pack_W<<<4096, 256>>>(W);

    dim3 g1(G4 / 128, (BB * TT) / 128);  // (32, 256)
    embed_gemm_tf32<<<g1, 256>>>(ids, E, bias);

    lstm_persist<<<NBLK, 256, 107520>>>(ids, out);
}

// round 8
// speedup vs baseline: 5.4841x; 1.4661x over previous
#include <cuda_runtime.h>
#include <cuda_fp16.h>
#include <math.h>
#include <stdint.h>

#define BB 64
#define TT 512
#define DD 512
#define HH 1024
#define G4 4096  // 4*H
#define NBLK 128

// Scratch (allocation-free rule: __device__ globals only)
__device__ float    g_xw[(size_t)BB * TT * G4];   // 512 MB
__device__ __half   g_hh[2][BB * HH];             // ping-pong hidden state (fp16)
__device__ uint2    g_Uh[128 * 4 * 64 * 32];      // 8 MB: U fp16 fragment layout
__device__ float2   g_Wpack[512 * 64 * 32];       // 8 MB: W tf32 fragment layout (embed)
__device__ unsigned g_cnt;

__device__ __forceinline__ float sigf(float x) {
    return 1.0f / (1.0f + __expf(-x));
}

__device__ __forceinline__ void mma_tf32(float d[4],
                                         uint32_t a0, uint32_t a1, uint32_t a2, uint32_t a3,
                                         uint32_t b0, uint32_t b1) {
    asm volatile(
        "mma.sync.aligned.m16n8k8.row.col.f32.tf32.tf32.f32 "
        "{%0,%1,%2,%3}, {%4,%5,%6,%7}, {%8,%9}, {%0,%1,%2,%3};\n"
        : "+f"(d[0]), "+f"(d[1]), "+f"(d[2]), "+f"(d[3])
        : "r"(a0), "r"(a1), "r"(a2), "r"(a3), "r"(b0), "r"(b1));
}

__device__ __forceinline__ void mma_f16(float d[4],
                                        uint32_t a0, uint32_t a1, uint32_t a2, uint32_t a3,
                                        uint32_t b0, uint32_t b1) {
    asm volatile(
        "mma.sync.aligned.m16n8k16.row.col.f32.f16.f16.f32 "
        "{%0,%1,%2,%3}, {%4,%5,%6,%7}, {%8,%9}, {%0,%1,%2,%3};\n"
        : "+f"(d[0]), "+f"(d[1]), "+f"(d[2]), "+f"(d[3])
        : "r"(a0), "r"(a1), "r"(a2), "r"(a3), "r"(b0), "r"(b1));
}

__device__ __forceinline__ void ldsm4(uint32_t& r0, uint32_t& r1, uint32_t& r2, uint32_t& r3,
                                      uint32_t saddr) {
    asm volatile("ldmatrix.sync.aligned.m8n8.x4.shared.b16 {%0,%1,%2,%3}, [%4];"
                 : "=r"(r0), "=r"(r1), "=r"(r2), "=r"(r3) : "r"(saddr));
}

__device__ __forceinline__ unsigned ld_acq(unsigned* p) {
    unsigned v;
    asm volatile("ld.acquire.gpu.u32 %0, [%1];" : "=r"(v) : "l"(p) : "memory");
    return v;
}

__device__ __forceinline__ uint32_t smem_u32(const void* p) {
    uint32_t a;
    asm("{ .reg .u64 t; cvta.to.shared.u64 t, %1; cvt.u32.u64 %0, t; }" : "=r"(a) : "l"(p));
    return a;
}

// ---------------------------------------------------------------------------
__global__ void reset_bar() { g_cnt = 0; }

__global__ void init_state() {
    int i = blockIdx.x * blockDim.x + threadIdx.x;
    if (i < BB * HH) g_hh[0][i] = __float2half(0.0f);
}

// ---------------------------------------------------------------------------
// pack_Uh: U[1024][4096] -> [jb(128)][gate(4)][k16(64)][lane(32)] uint2 (fp16)
// ---------------------------------------------------------------------------
__global__ __launch_bounds__(256) void pack_Uh(const float* __restrict__ U) {
    int idx = blockIdx.x * blockDim.x + threadIdx.x;  // < 1048576
    int lane = idx & 31;
    int k16  = (idx >> 5) & 63;
    int gate = (idx >> 11) & 3;
    int jb   = idx >> 13;
    int col = gate * HH + jb * 8 + (lane >> 2);
    int r0  = k16 * 16 + (lane & 3) * 2;
    float u00 = U[(size_t)r0 * G4 + col];
    float u01 = U[(size_t)(r0 + 1) * G4 + col];
    float u10 = U[(size_t)(r0 + 8) * G4 + col];
    float u11 = U[(size_t)(r0 + 9) * G4 + col];
    __half2 h0 = __floats2half2_rn(u00, u01);
    __half2 h1 = __floats2half2_rn(u10, u11);
    uint2 v;
    v.x = *(uint32_t*)&h0;
    v.y = *(uint32_t*)&h1;
    g_Uh[idx] = v;
}

// ---------------------------------------------------------------------------
// pack_W: W[512][4096] -> [ntile(512)][kg(64)][lane(32)] float2 (tf32)
// ---------------------------------------------------------------------------
__global__ __launch_bounds__(256) void pack_W(const float* __restrict__ W) {
    int idx = blockIdx.x * blockDim.x + threadIdx.x;
    int lane  = idx & 31;
    int kg    = (idx >> 5) & 63;
    int ntile = idx >> 11;
    int col = ntile * 8 + (lane >> 2);
    int r0  = kg * 8 + (lane & 3);
    float u0 = W[(size_t)r0 * G4 + col];
    float u1 = W[(size_t)(r0 + 4) * G4 + col];
    uint32_t t0, t1;
    asm("cvt.rna.tf32.f32 %0, %1;" : "=r"(t0) : "f"(u0));
    asm("cvt.rna.tf32.f32 %0, %1;" : "=r"(t1) : "f"(u1));
    g_Wpack[idx] = make_float2(__uint_as_float(t0), __uint_as_float(t1));
}

// ---------------------------------------------------------------------------
// embed GEMM (tf32 mma.sync): xw = E[ids] @ W + bias   (proven, unchanged)
// ---------------------------------------------------------------------------
__global__ __launch_bounds__(256, 1) void embed_gemm_tf32(
    const int* __restrict__ ids,
    const float* __restrict__ E,
    const float* __restrict__ bias)
{
    __shared__ int   ids_s[128];
    __shared__ float As[2][128][32];

    const int m0 = blockIdx.y * 128;
    const int n0 = blockIdx.x * 128;
    const int tid  = threadIdx.x;
    const int warp = tid >> 5;
    const int lane = tid & 31;
    const int mw   = warp >> 2;
    const int nw   = warp & 3;

    if (tid < 128) ids_s[tid] = ids[m0 + tid];
    __syncthreads();

    const int row7   = lane & 7;
    const int cghalf = (lane >> 4) & 1;
    const int rbase  = (lane & 7) + ((lane >> 3) & 1) * 8;

    float d[4][4][4];
#pragma unroll
    for (int a = 0; a < 4; a++)
#pragma unroll
        for (int b = 0; b < 4; b++)
#pragma unroll
            for (int c = 0; c < 4; c++) d[a][b][c] = 0.0f;

    float4 va[4];
#pragma unroll
    for (int i = 0; i < 4; i++) {
        int f4 = tid + i * 256;
        int row = f4 >> 3, cg = f4 & 7;
        va[i] = *(const float4*)&E[(size_t)ids_s[row] * DD + cg * 4];
    }
#pragma unroll
    for (int i = 0; i < 4; i++) {
        int f4 = tid + i * 256;
        int row = f4 >> 3, cg = f4 & 7;
        *(float4*)&As[0][row][(cg ^ (row & 7)) * 4] = va[i];
    }
    __syncthreads();

    const float2* wp = &g_Wpack[((size_t)(n0 >> 3) + nw * 4) * 64 * 32 + lane];

#pragma unroll 1
    for (int chunk = 0; chunk < 16; chunk++) {
        const int cur = chunk & 1;
        if (chunk < 15) {
            const int k0 = (chunk + 1) * 32;
#pragma unroll
            for (int i = 0; i < 4; i++) {
                int f4 = tid + i * 256;
                int row = f4 >> 3, cg = f4 & 7;
                va[i] = *(const float4*)&E[(size_t)ids_s[row] * DD + k0 + cg * 4];
            }
        }
        float2 bfr[4][4];
#pragma unroll
        for (int nt = 0; nt < 4; nt++)
#pragma unroll
            for (int ki = 0; ki < 4; ki++)
                bfr[nt][ki] = wp[(size_t)nt * 2048 + (chunk * 4 + ki) * 32];

        uint32_t abase = (uint32_t)__cvta_generic_to_shared(&As[cur][0][0]);
#pragma unroll
        for (int ki = 0; ki < 4; ki++) {
#pragma unroll
            for (int mt = 0; mt < 4; mt++) {
                int rowb = mw * 64 + mt * 16 + rbase;
                uint32_t a0, a1, a2, a3;
                ldsm4(a0, a1, a2, a3,
                      abase + rowb * 128 + (((2 * ki + cghalf) ^ row7) << 4));
#pragma unroll
                for (int nt = 0; nt < 4; nt++)
                    mma_tf32(d[mt][nt], a0, a1, a2, a3,
                             __float_as_uint(bfr[nt][ki].x),
                             __float_as_uint(bfr[nt][ki].y));
            }
        }
        if (chunk < 15) {
#pragma unroll
            for (int i = 0; i < 4; i++) {
                int f4 = tid + i * 256;
                int row = f4 >> 3, cg = f4 & 7;
                *(float4*)&As[cur ^ 1][row][(cg ^ (row & 7)) * 4] = va[i];
            }
        }
        __syncthreads();
    }

    const int rr = lane >> 2;
    const int cc = (lane & 3) * 2;
#pragma unroll
    for (int nt = 0; nt < 4; nt++) {
        int col = n0 + nw * 32 + nt * 8 + cc;
        float2 bv = *(const float2*)&bias[col];
#pragma unroll
        for (int mt = 0; mt < 4; mt++) {
            int row = m0 + mw * 64 + mt * 16 + rr;
            float2 v0 = make_float2(d[mt][nt][0] + bv.x, d[mt][nt][1] + bv.y);
            float2 v1 = make_float2(d[mt][nt][2] + bv.x, d[mt][nt][3] + bv.y);
            *(float2*)&g_xw[(size_t)row * G4 + col] = v0;
            *(float2*)&g_xw[(size_t)(row + 8) * G4 + col] = v1;
        }
    }
}

// ---------------------------------------------------------------------------
// Persistent recurrence (fp16 MMA, warp-specialized). 128 blocks x 512 thr.
// Warps 0-7: MMA consumers (mt = warp&3, gate pair nh = warp>>2).
// Warps 8-15: producers (stage h chunks into double-buffered smem).
// Fusion: all 512 threads, 1 (b, j) item each.
// SMEM: Us 64KB @0 | A bufs 2x16KB @65536 | zs [4][64][9]f @98304
// ---------------------------------------------------------------------------
__global__ __launch_bounds__(512, 1) void lstm_persist(
    const int* __restrict__ ids,
    float* __restrict__ out)
{
    extern __shared__ char smem_raw[];
    const uint32_t sbase = smem_u32(smem_raw);
    uint2* Us  = (uint2*)smem_raw;            // [4][64][32]
    float* zsp = (float*)(smem_raw + 98304);  // [4][64][9]

    const int tid  = threadIdx.x;
    const int warp = tid >> 5;
    const int lane = tid & 31;
    const int jb   = blockIdx.x;
    const int j0   = jb * 8;
    const bool producer = (warp >= 8);
    const int  ptid = tid & 255;              // producer-local id (warps 8-15)

    // MMA-warp constants
    const int mt = warp & 3;
    const int nh = warp >> 2;
    const int rowbase = mt * 16 + (lane & 7) + ((lane >> 3) & 1) * 8;
    const int row7    = rowbase & 7;
    const int kh      = (lane >> 4) & 1;
    const uint2* Ug0 = Us + (2 * nh + 0) * 64 * 32 + lane;
    const uint2* Ug1 = Us + (2 * nh + 1) * 64 * 32 + lane;

    // Fusion mapping: one item per thread
    const int b_ = tid >> 3;
    const int jj = tid & 7;
    float c_reg = 0.0f, h_reg = 0.0f;

    // Load U slice once (64 KB)
    {
        const uint4* src = (const uint4*)&g_Uh[(size_t)jb * 4 * 64 * 32];
        uint4* dst = (uint4*)smem_raw;
        for (int i = tid; i < 4096; i += 512) dst[i] = src[i];
    }
    __syncthreads();

#pragma unroll 1
    for (int t = 0; t < TT; t++) {
        const uint4* __restrict__ hin = (const uint4*)&g_hh[t & 1][0];
        __half* __restrict__ hout = &g_hh[(t + 1) & 1][0];

        // prefetch xw + mask (all threads, 1 item each)
        float xwv[4];
#pragma unroll
        for (int g = 0; g < 4; g++)
            xwv[g] = __ldcg(&g_xw[((size_t)(b_ * TT + t)) * G4 + g * HH + j0 + jj]);
        bool msk = __ldg(&ids[b_ * TT + t]) != 0;

        float d[2][4];
#pragma unroll
        for (int i = 0; i < 2; i++)
#pragma unroll
            for (int j = 0; j < 4; j++) d[i][j] = 0.0f;

        // prologue: producers stage chunk 0 into buf 0
        if (producer) {
            uint4 va[4];
#pragma unroll
            for (int i = 0; i < 4; i++) {
                int idx = ptid + i * 256;
                int row = idx >> 4, u = idx & 15;
                va[i] = __ldcg(&hin[row * 128 + u]);
            }
#pragma unroll
            for (int i = 0; i < 4; i++) {
                int idx = ptid + i * 256;
                int row = idx >> 4, u = idx & 15;
                *(uint4*)(smem_raw + 65536 + row * 256 + ((u ^ (row & 7)) << 4)) = va[i];
            }
        }
        __syncthreads();

#pragma unroll 1
        for (int c = 0; c < 8; c++) {
            if (producer) {
                if (c < 7) {
                    const int kq = (c + 1) * 16;
                    uint4 va[4];
#pragma unroll
                    for (int i = 0; i < 4; i++) {
                        int idx = ptid + i * 256;
                        int row = idx >> 4, u = idx & 15;
                        va[i] = __ldcg(&hin[row * 128 + kq + u]);
                    }
#pragma unroll
                    for (int i = 0; i < 4; i++) {
                        int idx = ptid + i * 256;
                        int row = idx >> 4, u = idx & 15;
                        *(uint4*)(smem_raw + 65536 + ((c + 1) & 1) * 16384
                                  + row * 256 + ((u ^ (row & 7)) << 4)) = va[i];
                    }
                }
            } else {
                uint32_t abase = sbase + 65536 + (c & 1) * 16384 + rowbase * 256;
#pragma unroll
                for (int ki = 0; ki < 8; ki++) {
                    uint32_t a0, a1, a2, a3;
                    ldsm4(a0, a1, a2, a3, abase + (((2 * ki + kh) ^ row7) << 4));
                    uint2 b0 = Ug0[(c * 8 + ki) * 32];
                    uint2 b1 = Ug1[(c * 8 + ki) * 32];
                    mma_f16(d[0], a0, a1, a2, a3, b0.x, b0.y);
                    mma_f16(d[1], a0, a1, a2, a3, b1.x, b1.y);
                }
            }
            __syncthreads();
        }

        // z exchange (MMA warps only)
        if (!producer) {
            int r = lane >> 2;
            int c2 = (lane & 3) * 2;
#pragma unroll
            for (int nt = 0; nt < 2; nt++) {
                int g = 2 * nh + nt;
                float* zr = zsp + g * 576;
                zr[(mt * 16 + r) * 9 + c2]         = d[nt][0];
                zr[(mt * 16 + r) * 9 + c2 + 1]     = d[nt][1];
                zr[(mt * 16 + 8 + r) * 9 + c2]     = d[nt][2];
                zr[(mt * 16 + 8 + r) * 9 + c2 + 1] = d[nt][3];
            }
        }
        __syncthreads();

        // gate fusion: all 512 threads, 1 item each
        {
            float zi = zsp[0 * 576 + b_ * 9 + jj] + xwv[0];
            float zf = zsp[1 * 576 + b_ * 9 + jj] + xwv[1];
            float zg = zsp[2 * 576 + b_ * 9 + jj] + xwv[2];
            float zo = zsp[3 * 576 + b_ * 9 + jj] + xwv[3];

            float ig = sigf(zi);
            float fg = sigf(zf);
            float gg = sigf(zg);   // reference: sigmoid (not tanh)
            float og = sigf(zo);

            float cn = fmaf(fg, c_reg, ig * gg);
            float hn = og * sigf(cn);

            float hv = msk ? hn : h_reg;
            float cv = msk ? cn : c_reg;
            h_reg = hv;
            c_reg = cv;

            hout[b_ * HH + j0 + jj] = __float2half(hv);
            __stcg(&out[((size_t)(b_ * TT + t)) * HH + j0 + jj], hv);
            if (t == TT - 1) {
                __stcg(&out[(size_t)BB * TT * HH + b_ * HH + j0 + jj], hv);
                __stcg(&out[(size_t)BB * TT * HH + BB * HH + b_ * HH + j0 + jj], cv);
            }
        }

        // grid barrier: single counter, release-add + acquire poll
        __syncthreads();
        if (tid == 0) {
            asm volatile("red.release.gpu.global.add.u32 [%0], 1;"
                         :: "l"(&g_cnt) : "memory");
            unsigned tgt = (unsigned)NBLK * (unsigned)(t + 1);
            while (ld_acq(&g_cnt) < tgt) { }
        }
        __syncthreads();
    }
}

extern "C" void kernel_launch(void* const* d_in, const int* in_sizes, int n_in,
                              void* d_out, int out_size) {
    const int*   ids  = (const int*)d_in[0];
    const float* E    = (const float*)d_in[1];
    const float* W    = (const float*)d_in[2];
    const float* U    = (const float*)d_in[3];
    const float* bias = (const float*)d_in[4];
    float* out = (float*)d_out;

    static bool attr_set = false;
    if (!attr_set) {
        cudaFuncSetAttribute(lstm_persist,
                             cudaFuncAttributeMaxDynamicSharedMemorySize, 107520);
        attr_set = true;
    }

    reset_bar<<<1, 1>>>();
    init_state<<<(BB * HH + 255) / 256, 256>>>();
    pack_Uh<<<4096, 256>>>(U);
    pack_W<<<4096, 256>>>(W);

    dim3 g1(G4 / 128, (BB * TT) / 128);  // (32, 256)
    embed_gemm_tf32<<<g1, 256>>>(ids, E, bias);

    lstm_persist<<<NBLK, 512, 107520>>>(ids, out);
}

// round 10
// speedup vs baseline: 6.4225x; 1.1711x over previous
#include <cuda_runtime.h>
#include <cuda_fp16.h>
#include <math.h>
#include <stdint.h>

#define BB 64
#define TT 512
#define VV 32000
#define DD 512
#define HH 1024
#define G4 4096  // 4*H
#define NBLK 128

// Scratch (allocation-free rule: __device__ globals only)
__device__ float    g_xw[(size_t)BB * TT * G4];   // 512 MB
__device__ __half   g_hh[2][BB * HH];             // ping-pong hidden state (fp16)
__device__ uint2    g_Uh[128 * 4 * 64 * 32];      // 8 MB: U fp16 fragment layout
__device__ uint2    g_Wh[512 * 32 * 32];          // 4 MB: W fp16 fragment layout
__device__ uint2    g_Eh[(size_t)VV * DD / 4];    // 32 MB: E in fp16
__device__ unsigned g_cnt;

__device__ __forceinline__ float sigf(float x) {
    return 1.0f / (1.0f + __expf(-x));
}

__device__ __forceinline__ void mma_f16(float d[4],
                                        uint32_t a0, uint32_t a1, uint32_t a2, uint32_t a3,
                                        uint32_t b0, uint32_t b1) {
    asm volatile(
        "mma.sync.aligned.m16n8k16.row.col.f32.f16.f16.f32 "
        "{%0,%1,%2,%3}, {%4,%5,%6,%7}, {%8,%9}, {%0,%1,%2,%3};\n"
        : "+f"(d[0]), "+f"(d[1]), "+f"(d[2]), "+f"(d[3])
        : "r"(a0), "r"(a1), "r"(a2), "r"(a3), "r"(b0), "r"(b1));
}

__device__ __forceinline__ void ldsm4(uint32_t& r0, uint32_t& r1, uint32_t& r2, uint32_t& r3,
                                      uint32_t saddr) {
    asm volatile("ldmatrix.sync.aligned.m8n8.x4.shared.b16 {%0,%1,%2,%3}, [%4];"
                 : "=r"(r0), "=r"(r1), "=r"(r2), "=r"(r3) : "r"(saddr));
}

__device__ __forceinline__ unsigned ld_acq(unsigned* p) {
    unsigned v;
    asm volatile("ld.acquire.gpu.u32 %0, [%1];" : "=r"(v) : "l"(p) : "memory");
    return v;
}

__device__ __forceinline__ uint32_t smem_u32(const void* p) {
    uint32_t a;
    asm("{ .reg .u64 t; cvta.to.shared.u64 t, %1; cvt.u32.u64 %0, t; }" : "=r"(a) : "l"(p));
    return a;
}

// ---------------------------------------------------------------------------
__global__ void reset_bar() { g_cnt = 0; }

__global__ void init_state() {
    int i = blockIdx.x * blockDim.x + threadIdx.x;
    if (i < BB * HH) g_hh[0][i] = __float2half(0.0f);
}

// ---------------------------------------------------------------------------
// pack_Eh: E fp32 -> fp16 (flat)
// ---------------------------------------------------------------------------
__global__ __launch_bounds__(256) void pack_Eh(const float* __restrict__ E) {
    size_t idx = (size_t)blockIdx.x * blockDim.x + threadIdx.x;  // < VV*DD/4
    float4 v = *(const float4*)&E[idx * 4];
    __half2 a = __floats2half2_rn(v.x, v.y);
    __half2 b = __floats2half2_rn(v.z, v.w);
    uint2 o;
    o.x = *(uint32_t*)&a;
    o.y = *(uint32_t*)&b;
    g_Eh[idx] = o;
}

// ---------------------------------------------------------------------------
// pack_Uh: U[1024][4096] -> [jb(128)][gate(4)][k16(64)][lane(32)] uint2 (fp16)
// ---------------------------------------------------------------------------
__global__ __launch_bounds__(256) void pack_Uh(const float* __restrict__ U) {
    int idx = blockIdx.x * blockDim.x + threadIdx.x;  // < 1048576
    int lane = idx & 31;
    int k16  = (idx >> 5) & 63;
    int gate = (idx >> 11) & 3;
    int jb   = idx >> 13;
    int col = gate * HH + jb * 8 + (lane >> 2);
    int r0  = k16 * 16 + (lane & 3) * 2;
    float u00 = U[(size_t)r0 * G4 + col];
    float u01 = U[(size_t)(r0 + 1) * G4 + col];
    float u10 = U[(size_t)(r0 + 8) * G4 + col];
    float u11 = U[(size_t)(r0 + 9) * G4 + col];
    __half2 h0 = __floats2half2_rn(u00, u01);
    __half2 h1 = __floats2half2_rn(u10, u11);
    uint2 v;
    v.x = *(uint32_t*)&h0;
    v.y = *(uint32_t*)&h1;
    g_Uh[idx] = v;
}

// ---------------------------------------------------------------------------
// pack_Wh: W[512][4096] -> [ntile(512)][k16(32)][lane(32)] uint2 (fp16)
// ---------------------------------------------------------------------------
__global__ __launch_bounds__(256) void pack_Wh(const float* __restrict__ W) {
    int idx = blockIdx.x * blockDim.x + threadIdx.x;  // < 524288
    int lane  = idx & 31;
    int k16   = (idx >> 5) & 31;
    int ntile = idx >> 10;
    int col = ntile * 8 + (lane >> 2);
    int r0  = k16 * 16 + (lane & 3) * 2;
    float u00 = W[(size_t)r0 * G4 + col];
    float u01 = W[(size_t)(r0 + 1) * G4 + col];
    float u10 = W[(size_t)(r0 + 8) * G4 + col];
    float u11 = W[(size_t)(r0 + 9) * G4 + col];
    __half2 h0 = __floats2half2_rn(u00, u01);
    __half2 h1 = __floats2half2_rn(u10, u11);
    uint2 v;
    v.x = *(uint32_t*)&h0;
    v.y = *(uint32_t*)&h1;
    g_Wh[idx] = v;
}

// ---------------------------------------------------------------------------
// embed GEMM (fp16 mma.sync m16n8k16): xw = E[ids] @ W + bias
// 128x128 tile, 256 thr, 8 warps (2m x 4n), 8 K-chunks of 64.
// A: fp16 E rows -> swizzled smem (128B rows) -> ldmatrix.x4. B: g_Wh LDG.
// ---------------------------------------------------------------------------
__global__ __launch_bounds__(256, 1) void embed_gemm_f16(
    const int* __restrict__ ids,
    const float* __restrict__ bias)
{
    __shared__ int ids_s[128];
    __shared__ __align__(16) char As[2][16384];  // 128 rows x 128B, x2

    const int m0 = blockIdx.y * 128;
    const int n0 = blockIdx.x * 128;
    const int tid  = threadIdx.x;
    const int warp = tid >> 5;
    const int lane = tid & 31;
    const int mw   = warp >> 2;
    const int nw   = warp & 3;

    if (tid < 128) ids_s[tid] = ids[m0 + tid];
    __syncthreads();

    const int base8 = (lane & 7) + ((lane >> 3) & 1) * 8;
    const int row7  = lane & 7;
    const int kh    = (lane >> 4) & 1;

    float d[4][4][4];
#pragma unroll
    for (int a = 0; a < 4; a++)
#pragma unroll
        for (int b = 0; b < 4; b++)
#pragma unroll
            for (int c = 0; c < 4; c++) d[a][b][c] = 0.0f;

    const uint4* Eh4 = (const uint4*)g_Eh;

    // stage chunk 0
    uint4 va[4];
#pragma unroll
    for (int i = 0; i < 4; i++) {
        int idx = tid + i * 256;
        int row = idx >> 3, u = idx & 7;
        va[i] = Eh4[(size_t)ids_s[row] * 64 + u];
    }
#pragma unroll
    for (int i = 0; i < 4; i++) {
        int idx = tid + i * 256;
        int row = idx >> 3, u = idx & 7;
        *(uint4*)(&As[0][row * 128 + ((u ^ (row & 7)) << 4)]) = va[i];
    }
    __syncthreads();

    const uint2* wp = &g_Wh[((size_t)(n0 >> 3) + nw * 4) * 32 * 32 + lane];

#pragma unroll 1
    for (int chunk = 0; chunk < 8; chunk++) {
        const int cur = chunk & 1;
        if (chunk < 7) {
            const int kq = (chunk + 1) * 8;
#pragma unroll
            for (int i = 0; i < 4; i++) {
                int idx = tid + i * 256;
                int row = idx >> 3, u = idx & 7;
                va[i] = Eh4[(size_t)ids_s[row] * 64 + kq + u];
            }
        }
        uint2 bfr[4][4];
#pragma unroll
        for (int nt = 0; nt < 4; nt++)
#pragma unroll
            for (int ki = 0; ki < 4; ki++)
                bfr[nt][ki] = wp[(size_t)nt * 1024 + (chunk * 4 + ki) * 32];

        uint32_t abase = (uint32_t)__cvta_generic_to_shared(&As[cur][0]);
#pragma unroll
        for (int ki = 0; ki < 4; ki++) {
#pragma unroll
            for (int mt = 0; mt < 4; mt++) {
                int rowb = mw * 64 + mt * 16 + base8;
                uint32_t a0, a1, a2, a3;
                ldsm4(a0, a1, a2, a3,
                      abase + rowb * 128 + (((2 * ki + kh) ^ row7) << 4));
#pragma unroll
                for (int nt = 0; nt < 4; nt++)
                    mma_f16(d[mt][nt], a0, a1, a2, a3,
                            bfr[nt][ki].x, bfr[nt][ki].y);
            }
        }
        if (chunk < 7) {
#pragma unroll
            for (int i = 0; i < 4; i++) {
                int idx = tid + i * 256;
                int row = idx >> 3, u = idx & 7;
                *(uint4*)(&As[cur ^ 1][row * 128 + ((u ^ (row & 7)) << 4)]) = va[i];
            }
        }
        __syncthreads();
    }

    // epilogue: + bias, write g_xw (fragment: c0,c1 @ (r, 2c), c2,c3 @ (r+8, 2c))
    const int rr = lane >> 2;
    const int cc = (lane & 3) * 2;
#pragma unroll
    for (int nt = 0; nt < 4; nt++) {
        int col = n0 + nw * 32 + nt * 8 + cc;
        float2 bv = *(const float2*)&bias[col];
#pragma unroll
        for (int mt = 0; mt < 4; mt++) {
            int row = m0 + mw * 64 + mt * 16 + rr;
            float2 v0 = make_float2(d[mt][nt][0] + bv.x, d[mt][nt][1] + bv.y);
            float2 v1 = make_float2(d[mt][nt][2] + bv.x, d[mt][nt][3] + bv.y);
            *(float2*)&g_xw[(size_t)row * G4 + col] = v0;
            *(float2*)&g_xw[(size_t)(row + 8) * G4 + col] = v1;
        }
    }
}

// ---------------------------------------------------------------------------
// Persistent recurrence (fp16 MMA, warp-specialized). 128 blocks x 512 thr.
// Warps 0-7: MMA consumers. Warps 8-15: producers. 4 K-chunks of 256.
// SMEM: Us 64KB @0 | A bufs 2x32KB @65536 | zs [4][64][9]f @131072
// ---------------------------------------------------------------------------
__global__ __launch_bounds__(512, 1) void lstm_persist(
    const int* __restrict__ ids,
    float* __restrict__ out)
{
    extern __shared__ char smem_raw[];
    const uint32_t sbase = smem_u32(smem_raw);
    uint2* Us  = (uint2*)smem_raw;             // [4][64][32]
    float* zsp = (float*)(smem_raw + 131072);  // [4][64][9]

    const int tid  = threadIdx.x;
    const int warp = tid >> 5;
    const int lane = tid & 31;
    const int jb   = blockIdx.x;
    const int j0   = jb * 8;
    const bool producer = (warp >= 8);
    const int  ptid = tid & 255;

    // MMA-warp constants
    const int mt = warp & 3;
    const int nh = warp >> 2;
    const int rowbase = mt * 16 + (lane & 7) + ((lane >> 3) & 1) * 8;
    const int row7    = rowbase & 7;
    const int kh      = (lane >> 4) & 1;
    const uint2* Ug0 = Us + (2 * nh + 0) * 64 * 32 + lane;
    const uint2* Ug1 = Us + (2 * nh + 1) * 64 * 32 + lane;

    // Fusion: one (b, j) item per thread
    const int b_ = tid >> 3;
    const int jj = tid & 7;
    float c_reg = 0.0f, h_reg = 0.0f;

    // Load U slice once (64 KB)
    {
        const uint4* src = (const uint4*)&g_Uh[(size_t)jb * 4 * 64 * 32];
        uint4* dst = (uint4*)smem_raw;
        for (int i = tid; i < 4096; i += 512) dst[i] = src[i];
    }
    __syncthreads();

#pragma unroll 1
    for (int t = 0; t < TT; t++) {
        const uint4* __restrict__ hin = (const uint4*)&g_hh[t & 1][0];
        __half* __restrict__ hout = &g_hh[(t + 1) & 1][0];

        // prefetch xw + mask
        float xwv[4];
#pragma unroll
        for (int g = 0; g < 4; g++)
            xwv[g] = __ldcg(&g_xw[((size_t)(b_ * TT + t)) * G4 + g * HH + j0 + jj]);
        bool msk = __ldg(&ids[b_ * TT + t]) != 0;

        float d[2][4];
#pragma unroll
        for (int i = 0; i < 2; i++)
#pragma unroll
            for (int j = 0; j < 4; j++) d[i][j] = 0.0f;

        // prologue: producers stage chunk 0 into buf 0 (64 rows x 32 units)
        if (producer) {
            uint4 va[8];
#pragma unroll
            for (int i = 0; i < 8; i++) {
                int idx = ptid + i * 256;
                int row = idx >> 5, u = idx & 31;
                va[i] = __ldcg(&hin[row * 128 + u]);
            }
#pragma unroll
            for (int i = 0; i < 8; i++) {
                int idx = ptid + i * 256;
                int row = idx >> 5, u = idx & 31;
                *(uint4*)(smem_raw + 65536 + row * 512 + ((u ^ (row & 7)) << 4)) = va[i];
            }
        }
        __syncthreads();

#pragma unroll 1
        for (int c = 0; c < 4; c++) {
            if (producer) {
                if (c < 3) {
                    const int kq = (c + 1) * 32;
                    uint4 va[8];
#pragma unroll
                    for (int i = 0; i < 8; i++) {
                        int idx = ptid + i * 256;
                        int row = idx >> 5, u = idx & 31;
                        va[i] = __ldcg(&hin[row * 128 + kq + u]);
                    }
#pragma unroll
                    for (int i = 0; i < 8; i++) {
                        int idx = ptid + i * 256;
                        int row = idx >> 5, u = idx & 31;
                        *(uint4*)(smem_raw + 65536 + ((c + 1) & 1) * 32768
                                  + row * 512 + ((u ^ (row & 7)) << 4)) = va[i];
                    }
                }
            } else {
                uint32_t abase = sbase + 65536 + (c & 1) * 32768 + rowbase * 512;
#pragma unroll
                for (int ki = 0; ki < 16; ki++) {
                    uint32_t a0, a1, a2, a3;
                    ldsm4(a0, a1, a2, a3, abase + (((2 * ki + kh) ^ row7) << 4));
                    uint2 b0 = Ug0[(c * 16 + ki) * 32];
                    uint2 b1 = Ug1[(c * 16 + ki) * 32];
                    mma_f16(d[0], a0, a1, a2, a3, b0.x, b0.y);
                    mma_f16(d[1], a0, a1, a2, a3, b1.x, b1.y);
                }
            }
            __syncthreads();
        }

        // z exchange (MMA warps only)
        if (!producer) {
            int r = lane >> 2;
            int c2 = (lane & 3) * 2;
#pragma unroll
            for (int nt = 0; nt < 2; nt++) {
                int g = 2 * nh + nt;
                float* zr = zsp + g * 576;
                zr[(mt * 16 + r) * 9 + c2]         = d[nt][0];
                zr[(mt * 16 + r) * 9 + c2 + 1]     = d[nt][1];
                zr[(mt * 16 + 8 + r) * 9 + c2]     = d[nt][2];
                zr[(mt * 16 + 8 + r) * 9 + c2 + 1] = d[nt][3];
            }
        }
        __syncthreads();

        // gate fusion: all 512 threads
        {
            float zi = zsp[0 * 576 + b_ * 9 + jj] + xwv[0];
            float zf = zsp[1 * 576 + b_ * 9 + jj] + xwv[1];
            float zg = zsp[2 * 576 + b_ * 9 + jj] + xwv[2];
            float zo = zsp[3 * 576 + b_ * 9 + jj] + xwv[3];

            float ig = sigf(zi);
            float fg = sigf(zf);
            float gg = sigf(zg);   // reference: sigmoid (not tanh)
            float og = sigf(zo);

            float cn = fmaf(fg, c_reg, ig * gg);
            float hn = og * sigf(cn);

            float hv = msk ? hn : h_reg;
            float cv = msk ? cn : c_reg;
            h_reg = hv;
            c_reg = cv;

            hout[b_ * HH + j0 + jj] = __float2half(hv);
            __stcg(&out[((size_t)(b_ * TT + t)) * HH + j0 + jj], hv);
            if (t == TT - 1) {
                __stcg(&out[(size_t)BB * TT * HH + b_ * HH + j0 + jj], hv);
                __stcg(&out[(size_t)BB * TT * HH + BB * HH + b_ * HH + j0 + jj], cv);
            }
        }

        // grid barrier: single counter
        __syncthreads();
        if (tid == 0) {
            asm volatile("red.release.gpu.global.add.u32 [%0], 1;"
                         :: "l"(&g_cnt) : "memory");
            unsigned tgt = (unsigned)NBLK * (unsigned)(t + 1);
            while (ld_acq(&g_cnt) < tgt) { }
        }
        __syncthreads();
    }
}

extern "C" void kernel_launch(void* const* d_in, const int* in_sizes, int n_in,
                              void* d_out, int out_size) {
    const int*   ids  = (const int*)d_in[0];
    const float* E    = (const float*)d_in[1];
    const float* W    = (const float*)d_in[2];
    const float* U    = (const float*)d_in[3];
    const float* bias = (const float*)d_in[4];
    float* out = (float*)d_out;

    static bool attr_set = false;
    if (!attr_set) {
        cudaFuncSetAttribute(lstm_persist,
                             cudaFuncAttributeMaxDynamicSharedMemorySize, 140288);
        attr_set = true;
    }

    reset_bar<<<1, 1>>>();
    init_state<<<(BB * HH + 255) / 256, 256>>>();
    pack_Eh<<<VV * DD / 4 / 256, 256>>>(E);
    pack_Uh<<<4096, 256>>>(U);
    pack_Wh<<<2048, 256>>>(W);

    dim3 g1(G4 / 128, (BB * TT) / 128);  // (32, 256)
    embed_gemm_f16<<<g1, 256>>>(ids, bias);

    lstm_persist<<<NBLK, 512, 140288>>>(ids, out);
}